// round 6
// baseline (speedup 1.0000x reference)
#include <cuda_runtime.h>
#include <cstdint>
#include <cstddef>

#define SEQ   4096
#define BATCH 256
#define NS    16
#define MS    8
#define US    4
#define LCH   8           // chunk length
#define NCH   512         // chunks
#define GRP   16          // chunks per group
#define NGRP  32          // groups
#define GQ    448         // gain scalars per t: M(256)|N(64)|K(128)

// ---------------- device scratch ----------------
__device__ __align__(16) float2 d_G2[(size_t)SEQ * GQ];   // duplicated (g,g) pairs
__device__ __align__(16) float2 d_Gst2[GQ];
__device__ int d_tconv;
__device__ __align__(16) float d_Phi[NCH * 256];
__device__ __align__(16) float d_Psi[NGRP * 256];
__device__ __align__(16) float d_V  [(size_t)NCH  * BATCH * NS];
__device__ __align__(16) float d_GV [(size_t)NGRP * BATCH * NS];
__device__ __align__(16) float d_GS [(size_t)NGRP * BATCH * NS];
__device__ __align__(16) float d_Sst[(size_t)NCH  * BATCH * NS];

// ---------------- f32x2 helpers ----------------
__device__ __forceinline__ unsigned long long ffma2(unsigned long long a, unsigned long long b, unsigned long long c) {
    unsigned long long d;
    asm("fma.rn.f32x2 %0, %1, %2, %3;" : "=l"(d) : "l"(a), "l"(b), "l"(c));
    return d;
}
__device__ __forceinline__ unsigned long long fmul2(unsigned long long a, unsigned long long b) {
    unsigned long long d;
    asm("mul.rn.f32x2 %0, %1, %2;" : "=l"(d) : "l"(a), "l"(b));
    return d;
}
__device__ __forceinline__ unsigned long long pack2(float x, float y) {
    unsigned long long r;
    asm("mov.b64 %0, {%1, %2};" : "=l"(r) : "f"(x), "f"(y));
    return r;
}
__device__ __forceinline__ void unpk2(unsigned long long v, float& lo, float& hi) {
    asm("mov.b64 {%0, %1}, %2;" : "=f"(lo), "=f"(hi) : "l"(v));
}

// =========================================================================
// Kernel 1: serial Riccati recursion (one block), 6 barriers/step
// =========================================================================
__global__ void __launch_bounds__(256) riccati_kernel(
    const float* __restrict__ A, const float* __restrict__ B,
    const float* __restrict__ C, const float* __restrict__ Q,
    const float* __restrict__ R)
{
    __shared__ float sA[256], sB[64], sC[128], sQ[256], sR[64];
    __shared__ float sCA[128], sCB[32], sCQ[128], sSR0[64];
    __shared__ float sP[256], sT1[256], sPp[256], sCT[128], sW[128], sK[128], sSm[64], sSi[64];

    const int tid = threadIdx.x;
    const int i  = tid >> 4;
    const int jc = tid & 15;

    sA[tid] = A[tid];
    sQ[tid] = Q[tid];
    if (tid < 64)  { sB[tid] = B[tid]; sR[tid] = R[tid]; }
    if (tid < 128) sC[tid] = C[tid];
    sP[tid] = (i == jc) ? 1.0f : 0.0f;   // P0 = I
    __syncthreads();

    if (tid < 128) {                      // CA = C*A, CQ = C*Q  (8x16)
        float a = 0.f, q = 0.f;
        int m = tid >> 4, jj = tid & 15;
        #pragma unroll
        for (int k = 0; k < 16; ++k) {
            a += sC[m * 16 + k] * sA[k * 16 + jj];
            q += sC[m * 16 + k] * sQ[k * 16 + jj];
        }
        sCA[tid] = a; sCQ[tid] = q;
    }
    if (tid < 32) {                       // CB = C*B  (8x4)
        float a = 0.f;
        #pragma unroll
        for (int k = 0; k < 16; ++k) a += sC[(tid >> 2) * 16 + k] * sB[k * 4 + (tid & 3)];
        sCB[tid] = a;
    }
    __syncthreads();
    if (tid < 64) {                       // SR0 = CQ*C^T + R (8x8)
        int m = tid >> 3, n = tid & 7;
        float s = sR[tid];
        #pragma unroll
        for (int k = 0; k < 16; ++k) s += sCQ[m * 16 + k] * sC[n * 16 + k];
        sSR0[tid] = s;
    }
    __syncthreads();

    int tconv = SEQ;
    for (int t = 1; t < SEQ; ++t) {
        // (1) T1 = A * P
        float a = 0.f;
        #pragma unroll
        for (int k = 0; k < 16; ++k) a += sA[i * 16 + k] * sP[k * 16 + jc];
        sT1[tid] = a;
        __syncthreads();
        // (2) Ppri = T1*A^T + Q (all)  ;  CT = C*T1 (tid<128)
        a = sQ[tid];
        #pragma unroll
        for (int k = 0; k < 16; ++k) a += sT1[i * 16 + k] * sA[jc * 16 + k];
        sPp[tid] = a;
        if (tid < 128) {
            int m = tid >> 4, jj = tid & 15;
            float w = 0.f;
            #pragma unroll
            for (int k = 0; k < 16; ++k) w += sC[m * 16 + k] * sT1[k * 16 + jj];
            sCT[tid] = w;
        }
        __syncthreads();
        // (3) W = CT*A^T + CQ (tid<128)  ;  S = CT*CA^T + SR0 (tid 128..191)
        if (tid < 128) {
            int m = tid >> 4, jj = tid & 15;
            float w = sCQ[tid];
            #pragma unroll
            for (int k = 0; k < 16; ++k) w += sCT[m * 16 + k] * sA[jj * 16 + k];
            sW[tid] = w;
        } else if (tid < 192) {
            int q = tid - 128, m = q >> 3, n = q & 7;
            float s = sSR0[q];
            #pragma unroll
            for (int k = 0; k < 16; ++k) s += sCT[m * 16 + k] * sCA[n * 16 + k];
            sSm[q] = s;
        }
        __syncthreads();
        // (4) Sinv: warp-synchronous Gauss-Jordan (8 lanes, SPD)
        if (tid < 8) {
            float row[16];
            #pragma unroll
            for (int c = 0; c < 8; ++c) { row[c] = sSm[tid * 8 + c]; row[c + 8] = (c == tid) ? 1.f : 0.f; }
            #pragma unroll
            for (int p = 0; p < 8; ++p) {
                float pv  = __shfl_sync(0xFFu, row[p], p, 8);
                float f   = row[p];
                float inv = 1.0f / pv;
                #pragma unroll
                for (int c = 0; c < 16; ++c) {
                    float pr = __shfl_sync(0xFFu, row[c], p, 8) * inv;
                    row[c] = (tid == p) ? pr : (row[c] - f * pr);
                }
            }
            #pragma unroll
            for (int c = 0; c < 8; ++c) sSi[tid * 8 + c] = row[c + 8];
        }
        __syncthreads();
        // (5) K = W^T * Sinv  (16x8)
        if (tid < 128) {
            int ii = tid >> 3, m = tid & 7;
            float kk = 0.f;
            #pragma unroll
            for (int n = 0; n < 8; ++n) kk += sW[n * 16 + ii] * sSi[n * 8 + m];
            sK[tid] = kk;
        }
        __syncthreads();
        // (6) outputs + Ppost + convergence
        {
            float mm = sA[tid];                         // M = A - K*CA
            #pragma unroll
            for (int m = 0; m < 8; ++m) mm -= sK[i * 8 + m] * sCA[m * 16 + jc];
            d_G2[(size_t)t * GQ + tid] = make_float2(mm, mm);
        }
        if (tid < 64) {                                 // N = B - K*CB
            int ii = tid >> 2, u = tid & 3;
            float nn = sB[tid];
            #pragma unroll
            for (int m = 0; m < 8; ++m) nn -= sK[ii * 8 + m] * sCB[m * 4 + u];
            d_G2[(size_t)t * GQ + 256 + tid] = make_float2(nn, nn);
        }
        if (tid < 128) {
            float kk = sK[tid];
            d_G2[(size_t)t * GQ + 320 + tid] = make_float2(kk, kk);
        }
        float pn = sPp[tid];                            // Ppost = Ppri - K*W
        #pragma unroll
        for (int m = 0; m < 8; ++m) pn -= sK[i * 8 + m] * sW[m * 16 + jc];
        int pred = fabsf(pn - sP[tid]) < 1e-5f;
        sP[tid] = pn;
        int conv = __syncthreads_and(pred);
        if (conv) { tconv = t + 1; break; }
    }
    __syncthreads();
    const int tlast = (tconv < SEQ) ? (tconv - 1) : (SEQ - 1);
    for (int q = tid; q < GQ; q += 256) d_Gst2[q] = d_G2[(size_t)tlast * GQ + q];
    if (tid == 0) d_tconv = tconv;
}

// =========================================================================
// Kernel 2: broadcast steady gains to t >= tconv
// =========================================================================
__global__ void fill_kernel()
{
    const int t = blockIdx.x + 1;        // 1..4095
    if (t < d_tconv) return;
    const int q = threadIdx.x;           // 224 threads * float4 = 448 float2
    reinterpret_cast<float4*>(&d_G2[(size_t)t * GQ])[q] =
        reinterpret_cast<const float4*>(d_Gst2)[q];
}

// =========================================================================
// Kernel 3: per-chunk transition matrices Phi_j (M scalars = .x of pairs)
// =========================================================================
__global__ void __launch_bounds__(256) phi_kernel()
{
    __shared__ float sPhi[256], sM[256];
    const int j = blockIdx.x, tid = threadIdx.x;
    const int i = tid >> 4, jc = tid & 15;
    const int t0 = j * LCH + 1;
    sPhi[tid] = d_G2[(size_t)t0 * GQ + tid].x;
    __syncthreads();
    for (int s = 1; s < LCH; ++s) {
        const int t = t0 + s;
        if (t >= SEQ) break;
        sM[tid] = d_G2[(size_t)t * GQ + tid].x;
        __syncthreads();
        float a = 0.f;
        #pragma unroll
        for (int k = 0; k < 16; ++k) a += sM[i * 16 + k] * sPhi[k * 16 + jc];
        __syncthreads();
        sPhi[tid] = a;
        __syncthreads();
    }
    d_Phi[j * 256 + tid] = sPhi[tid];
}

// =========================================================================
// Kernel 4: per-group transition matrices Psi_g = prod of 16 Phi
// =========================================================================
__global__ void __launch_bounds__(256) psi_kernel()
{
    __shared__ float sPsi[256], sM[256];
    const int g = blockIdx.x, tid = threadIdx.x;
    const int i = tid >> 4, jc = tid & 15;
    sPsi[tid] = d_Phi[(g * GRP) * 256 + tid];
    __syncthreads();
    for (int c = 1; c < GRP; ++c) {
        sM[tid] = d_Phi[(g * GRP + c) * 256 + tid];
        __syncthreads();
        float a = 0.f;
        #pragma unroll
        for (int k = 0; k < 16; ++k) a += sM[i * 16 + k] * sPsi[k * 16 + jc];
        __syncthreads();
        sPsi[tid] = a;
        __syncthreads();
    }
    d_Psi[g * 256 + tid] = sPsi[tid];
}

// =========================================================================
// packed affine step:  x <- M x + N u + K z   for a batch pair
// =========================================================================
__device__ __forceinline__ void kstep2(unsigned long long x[NS],
                                       const unsigned long long* __restrict__ g,
                                       const unsigned long long zz[MS],
                                       const unsigned long long uu[US])
{
    unsigned long long acc[NS];
    #pragma unroll
    for (int i = 0; i < NS; ++i) {
        const unsigned long long* gm = g + i * 16;
        const unsigned long long* gn = g + 256 + i * 4;
        const unsigned long long* gk = g + 320 + i * 8;
        unsigned long long a = fmul2(gn[0], uu[0]);
        a = ffma2(gn[1], uu[1], a);
        a = ffma2(gn[2], uu[2], a);
        a = ffma2(gn[3], uu[3], a);
        #pragma unroll
        for (int m = 0; m < MS; ++m) a = ffma2(gk[m], zz[m], a);
        #pragma unroll
        for (int k = 0; k < NS; ++k) a = ffma2(gm[k], x[k], a);
        acc[i] = a;
    }
    #pragma unroll
    for (int i = 0; i < NS; ++i) x[i] = acc[i];
}

__device__ __forceinline__ void load_zu2(const float* __restrict__ obs,
                                         const float* __restrict__ inp,
                                         int b0, int b1, int t,
                                         unsigned long long zz[MS], unsigned long long uu[US])
{
    const float4* z0p = reinterpret_cast<const float4*>(obs + ((size_t)b0 * SEQ + t) * MS);
    const float4* z1p = reinterpret_cast<const float4*>(obs + ((size_t)b1 * SEQ + t) * MS);
    float4 a0 = __ldg(z0p), a1 = __ldg(z0p + 1);
    float4 c0 = __ldg(z1p), c1 = __ldg(z1p + 1);
    zz[0] = pack2(a0.x, c0.x); zz[1] = pack2(a0.y, c0.y);
    zz[2] = pack2(a0.z, c0.z); zz[3] = pack2(a0.w, c0.w);
    zz[4] = pack2(a1.x, c1.x); zz[5] = pack2(a1.y, c1.y);
    zz[6] = pack2(a1.z, c1.z); zz[7] = pack2(a1.w, c1.w);
    float4 u0 = __ldg(reinterpret_cast<const float4*>(inp + ((size_t)b0 * SEQ + t) * US));
    float4 u1 = __ldg(reinterpret_cast<const float4*>(inp + ((size_t)b1 * SEQ + t) * US));
    uu[0] = pack2(u0.x, u1.x); uu[1] = pack2(u0.y, u1.y);
    uu[2] = pack2(u0.z, u1.z); uu[3] = pack2(u0.w, u1.w);
}

// =========================================================================
// Kernel 5: zero-start chunk responses (block = chunk, 128 thr x 2 batches)
// =========================================================================
__global__ void __launch_bounds__(128) vpass_kernel(const float* __restrict__ obs,
                                                    const float* __restrict__ inp)
{
    const int j = blockIdx.x, tid = threadIdx.x;
    const int b0 = tid, b1 = tid + 128;
    __shared__ __align__(16) unsigned long long gbuf[2][GQ];

    const int t0 = j * LCH + 1;
    const int steps = (t0 + LCH <= SEQ) ? LCH : (SEQ - t0);

    {   // prologue: stage gains for step 0
        const float4* src = reinterpret_cast<const float4*>(&d_G2[(size_t)t0 * GQ]);
        float4 r0 = __ldg(src + tid);
        reinterpret_cast<float4*>(gbuf[0])[tid] = r0;
        if (tid < 96) reinterpret_cast<float4*>(gbuf[0])[128 + tid] = __ldg(src + 128 + tid);
    }
    __syncthreads();

    unsigned long long x[NS];
    #pragma unroll
    for (int q = 0; q < NS; ++q) x[q] = 0ull;

    int p = 0;
    for (int s = 0; s < steps; ++s) {
        const int t = t0 + s;
        const bool more = (s + 1 < steps);
        float4 n0, n1;
        if (more) {
            const float4* nsrc = reinterpret_cast<const float4*>(&d_G2[(size_t)(t + 1) * GQ]);
            n0 = __ldg(nsrc + tid);
            if (tid < 96) n1 = __ldg(nsrc + 128 + tid);
        }
        unsigned long long zz[MS], uu[US];
        load_zu2(obs, inp, b0, b1, t, zz, uu);
        kstep2(x, gbuf[p], zz, uu);
        if (more) {
            reinterpret_cast<float4*>(gbuf[p ^ 1])[tid] = n0;
            if (tid < 96) reinterpret_cast<float4*>(gbuf[p ^ 1])[128 + tid] = n1;
        }
        __syncthreads();
        p ^= 1;
    }

    float lo[NS], hi[NS];
    #pragma unroll
    for (int q = 0; q < NS; ++q) unpk2(x[q], lo[q], hi[q]);
    float4* v0 = reinterpret_cast<float4*>(&d_V[((size_t)j * BATCH + b0) * NS]);
    float4* v1 = reinterpret_cast<float4*>(&d_V[((size_t)j * BATCH + b1) * NS]);
    v0[0] = make_float4(lo[0], lo[1], lo[2],  lo[3]);
    v0[1] = make_float4(lo[4], lo[5], lo[6],  lo[7]);
    v0[2] = make_float4(lo[8], lo[9], lo[10], lo[11]);
    v0[3] = make_float4(lo[12], lo[13], lo[14], lo[15]);
    v1[0] = make_float4(hi[0], hi[1], hi[2],  hi[3]);
    v1[1] = make_float4(hi[4], hi[5], hi[6],  hi[7]);
    v1[2] = make_float4(hi[8], hi[9], hi[10], hi[11]);
    v1[3] = make_float4(hi[12], hi[13], hi[14], hi[15]);
}

// ---------------- 16-lane shuffle matvec: a = v + P(row i) * s ----------------
__device__ __forceinline__ float affine16(const float* __restrict__ rowbase, float v, float s)
{
    const float4* pr = reinterpret_cast<const float4*>(rowbase);
    float4 p0 = __ldg(pr), p1 = __ldg(pr + 1), p2 = __ldg(pr + 2), p3 = __ldg(pr + 3);
    float a = v;
    a += p0.x * __shfl_sync(0xFFFFFFFFu, s, 0, 16)  + p0.y * __shfl_sync(0xFFFFFFFFu, s, 1, 16)
       + p0.z * __shfl_sync(0xFFFFFFFFu, s, 2, 16)  + p0.w * __shfl_sync(0xFFFFFFFFu, s, 3, 16);
    a += p1.x * __shfl_sync(0xFFFFFFFFu, s, 4, 16)  + p1.y * __shfl_sync(0xFFFFFFFFu, s, 5, 16)
       + p1.z * __shfl_sync(0xFFFFFFFFu, s, 6, 16)  + p1.w * __shfl_sync(0xFFFFFFFFu, s, 7, 16);
    a += p2.x * __shfl_sync(0xFFFFFFFFu, s, 8, 16)  + p2.y * __shfl_sync(0xFFFFFFFFu, s, 9, 16)
       + p2.z * __shfl_sync(0xFFFFFFFFu, s, 10, 16) + p2.w * __shfl_sync(0xFFFFFFFFu, s, 11, 16);
    a += p3.x * __shfl_sync(0xFFFFFFFFu, s, 12, 16) + p3.y * __shfl_sync(0xFFFFFFFFu, s, 13, 16)
       + p3.z * __shfl_sync(0xFFFFFFFFu, s, 14, 16) + p3.w * __shfl_sync(0xFFFFFFFFu, s, 15, 16);
    return a;
}

// =========================================================================
// Kernel 6a: group zero-responses GV_g (scan 16 chunks from zero)
// =========================================================================
__global__ void __launch_bounds__(256) gscanA_kernel()
{
    const int g = blockIdx.x >> 4, sub = blockIdx.x & 15;
    const int tid = threadIdx.x;
    const int b = sub * 16 + (tid >> 4);
    const int i = tid & 15;
    float s = 0.f;
    for (int c = 0; c < GRP; ++c) {
        const int ch = g * GRP + c;
        float v = __ldg(&d_V[((size_t)ch * BATCH + b) * NS + i]);
        s = affine16(&d_Phi[ch * 256 + i * 16], v, s);
    }
    d_GV[((size_t)g * BATCH + b) * NS + i] = s;
}

// =========================================================================
// Kernel 6b: serial scan over 32 groups -> group start states GS_g
// =========================================================================
__global__ void __launch_bounds__(256) gscanB_kernel(const float* __restrict__ x0)
{
    const int tid = threadIdx.x;
    const int b = blockIdx.x * 16 + (tid >> 4);
    const int i = tid & 15;
    float s = __ldg(x0 + i);
    for (int g = 0; g < NGRP; ++g) {
        d_GS[((size_t)g * BATCH + b) * NS + i] = s;
        float v = __ldg(&d_GV[((size_t)g * BATCH + b) * NS + i]);
        s = affine16(&d_Psi[g * 256 + i * 16], v, s);
    }
}

// =========================================================================
// Kernel 6c: within-group chunk start states -> d_Sst
// =========================================================================
__global__ void __launch_bounds__(256) gscanC_kernel()
{
    const int g = blockIdx.x >> 4, sub = blockIdx.x & 15;
    const int tid = threadIdx.x;
    const int b = sub * 16 + (tid >> 4);
    const int i = tid & 15;
    float s = __ldg(&d_GS[((size_t)g * BATCH + b) * NS + i]);
    for (int c = 0; c < GRP; ++c) {
        const int ch = g * GRP + c;
        d_Sst[((size_t)ch * BATCH + b) * NS + i] = s;
        float v = __ldg(&d_V[((size_t)ch * BATCH + b) * NS + i]);
        s = affine16(&d_Phi[ch * 256 + i * 16], v, s);
    }
}

// =========================================================================
// Kernel 7: final pass — rerun chunk from true start, emit outputs
// =========================================================================
__global__ void __launch_bounds__(128) outpass_kernel(const float* __restrict__ obs,
                                                      const float* __restrict__ inp,
                                                      float* __restrict__ out)
{
    const int j = blockIdx.x, tid = threadIdx.x;
    const int b0 = tid, b1 = tid + 128;
    __shared__ __align__(16) unsigned long long gbuf[2][GQ];

    const int t0 = j * LCH + 1;
    const int steps = (t0 + LCH <= SEQ) ? LCH : (SEQ - t0);

    {
        const float4* src = reinterpret_cast<const float4*>(&d_G2[(size_t)t0 * GQ]);
        float4 r0 = __ldg(src + tid);
        reinterpret_cast<float4*>(gbuf[0])[tid] = r0;
        if (tid < 96) reinterpret_cast<float4*>(gbuf[0])[128 + tid] = __ldg(src + 128 + tid);
    }

    unsigned long long x[NS];
    {
        const float4* s0 = reinterpret_cast<const float4*>(&d_Sst[((size_t)j * BATCH + b0) * NS]);
        const float4* s1 = reinterpret_cast<const float4*>(&d_Sst[((size_t)j * BATCH + b1) * NS]);
        float4 q0 = __ldg(s0), q1 = __ldg(s0 + 1), q2 = __ldg(s0 + 2), q3 = __ldg(s0 + 3);
        float4 r0 = __ldg(s1), r1 = __ldg(s1 + 1), r2 = __ldg(s1 + 2), r3 = __ldg(s1 + 3);
        x[0]  = pack2(q0.x, r0.x); x[1]  = pack2(q0.y, r0.y); x[2]  = pack2(q0.z, r0.z); x[3]  = pack2(q0.w, r0.w);
        x[4]  = pack2(q1.x, r1.x); x[5]  = pack2(q1.y, r1.y); x[6]  = pack2(q1.z, r1.z); x[7]  = pack2(q1.w, r1.w);
        x[8]  = pack2(q2.x, r2.x); x[9]  = pack2(q2.y, r2.y); x[10] = pack2(q2.z, r2.z); x[11] = pack2(q2.w, r2.w);
        x[12] = pack2(q3.x, r3.x); x[13] = pack2(q3.y, r3.y); x[14] = pack2(q3.z, r3.z); x[15] = pack2(q3.w, r3.w);
    }
    __syncthreads();

    if (j == 0) {      // out[b][0] = x0 = chunk-0 start state
        float lo[NS], hi[NS];
        #pragma unroll
        for (int q = 0; q < NS; ++q) unpk2(x[q], lo[q], hi[q]);
        float4* o0 = reinterpret_cast<float4*>(out + (size_t)b0 * SEQ * NS);
        float4* o1 = reinterpret_cast<float4*>(out + (size_t)b1 * SEQ * NS);
        o0[0] = make_float4(lo[0], lo[1], lo[2],  lo[3]);
        o0[1] = make_float4(lo[4], lo[5], lo[6],  lo[7]);
        o0[2] = make_float4(lo[8], lo[9], lo[10], lo[11]);
        o0[3] = make_float4(lo[12], lo[13], lo[14], lo[15]);
        o1[0] = make_float4(hi[0], hi[1], hi[2],  hi[3]);
        o1[1] = make_float4(hi[4], hi[5], hi[6],  hi[7]);
        o1[2] = make_float4(hi[8], hi[9], hi[10], hi[11]);
        o1[3] = make_float4(hi[12], hi[13], hi[14], hi[15]);
    }

    int p = 0;
    for (int s = 0; s < steps; ++s) {
        const int t = t0 + s;
        const bool more = (s + 1 < steps);
        float4 n0, n1;
        if (more) {
            const float4* nsrc = reinterpret_cast<const float4*>(&d_G2[(size_t)(t + 1) * GQ]);
            n0 = __ldg(nsrc + tid);
            if (tid < 96) n1 = __ldg(nsrc + 128 + tid);
        }
        unsigned long long zz[MS], uu[US];
        load_zu2(obs, inp, b0, b1, t, zz, uu);
        kstep2(x, gbuf[p], zz, uu);
        if (more) {
            reinterpret_cast<float4*>(gbuf[p ^ 1])[tid] = n0;
            if (tid < 96) reinterpret_cast<float4*>(gbuf[p ^ 1])[128 + tid] = n1;
        }
        float lo[NS], hi[NS];
        #pragma unroll
        for (int q = 0; q < NS; ++q) unpk2(x[q], lo[q], hi[q]);
        float4* o0 = reinterpret_cast<float4*>(out + ((size_t)b0 * SEQ + t) * NS);
        float4* o1 = reinterpret_cast<float4*>(out + ((size_t)b1 * SEQ + t) * NS);
        o0[0] = make_float4(lo[0], lo[1], lo[2],  lo[3]);
        o0[1] = make_float4(lo[4], lo[5], lo[6],  lo[7]);
        o0[2] = make_float4(lo[8], lo[9], lo[10], lo[11]);
        o0[3] = make_float4(lo[12], lo[13], lo[14], lo[15]);
        o1[0] = make_float4(hi[0], hi[1], hi[2],  hi[3]);
        o1[1] = make_float4(hi[4], hi[5], hi[6],  hi[7]);
        o1[2] = make_float4(hi[8], hi[9], hi[10], hi[11]);
        o1[3] = make_float4(hi[12], hi[13], hi[14], hi[15]);
        __syncthreads();
        p ^= 1;
    }
}

// =========================================================================
extern "C" void kernel_launch(void* const* d_in, const int* in_sizes, int n_in,
                              void* d_out, int out_size)
{
    (void)in_sizes; (void)n_in; (void)out_size;
    const float* obs = (const float*)d_in[0];
    const float* inp = (const float*)d_in[1];
    const float* A   = (const float*)d_in[2];
    const float* B   = (const float*)d_in[3];
    const float* C   = (const float*)d_in[4];
    const float* Q   = (const float*)d_in[5];
    const float* R   = (const float*)d_in[6];
    const float* x0  = (const float*)d_in[7];
    float* out = (float*)d_out;

    riccati_kernel<<<1, 256>>>(A, B, C, Q, R);
    fill_kernel<<<SEQ - 1, 224>>>();
    phi_kernel<<<NCH, 256>>>();
    psi_kernel<<<NGRP, 256>>>();
    vpass_kernel<<<NCH, 128>>>(obs, inp);
    gscanA_kernel<<<NGRP * 16, 256>>>();
    gscanB_kernel<<<BATCH / 16, 256>>>(x0);
    gscanC_kernel<<<NGRP * 16, 256>>>();
    outpass_kernel<<<NCH, 128>>>(obs, inp, out);
}

// round 7
// speedup vs baseline: 1.0460x; 1.0460x over previous
#include <cuda_runtime.h>
#include <cstdint>
#include <cstddef>

#define SEQ   4096
#define BATCH 256
#define NS    16
#define MS    8
#define US    4
#define LCH   8           // chunk length
#define NCH   512         // chunks
#define GRP   16          // chunks per group
#define NGRP  32          // groups
#define GQ    448         // gain scalars per t: M(256)|N(64)|K(128)

// ---------------- device scratch ----------------
__device__ __align__(16) float2 d_G2[(size_t)SEQ * GQ];   // duplicated (g,g) pairs
__device__ __align__(16) float2 d_Gst2[GQ];
__device__ int d_tconv;
__device__ __align__(16) float d_Phi[NCH * 256];
__device__ __align__(16) float d_Psi[NGRP * 256];
__device__ __align__(16) float d_V  [(size_t)NCH  * BATCH * NS];
__device__ __align__(16) float d_GV [(size_t)NGRP * BATCH * NS];
__device__ __align__(16) float d_GS [(size_t)NGRP * BATCH * NS];
__device__ __align__(16) float d_Sst[(size_t)NCH  * BATCH * NS];

// ---------------- f32x2 helpers ----------------
__device__ __forceinline__ unsigned long long ffma2(unsigned long long a, unsigned long long b, unsigned long long c) {
    unsigned long long d;
    asm("fma.rn.f32x2 %0, %1, %2, %3;" : "=l"(d) : "l"(a), "l"(b), "l"(c));
    return d;
}
__device__ __forceinline__ unsigned long long fmul2(unsigned long long a, unsigned long long b) {
    unsigned long long d;
    asm("mul.rn.f32x2 %0, %1, %2;" : "=l"(d) : "l"(a), "l"(b));
    return d;
}
__device__ __forceinline__ unsigned long long pack2(float x, float y) {
    unsigned long long r;
    asm("mov.b64 %0, {%1, %2};" : "=l"(r) : "f"(x), "f"(y));
    return r;
}
__device__ __forceinline__ void unpk2(unsigned long long v, float& lo, float& hi) {
    asm("mov.b64 {%0, %1}, %2;" : "=f"(lo), "=f"(hi) : "l"(v));
}

// =========================================================================
// Kernel 1: serial Riccati recursion (one block), 6 barriers/step
// =========================================================================
__global__ void __launch_bounds__(256) riccati_kernel(
    const float* __restrict__ A, const float* __restrict__ B,
    const float* __restrict__ C, const float* __restrict__ Q,
    const float* __restrict__ R)
{
    __shared__ float sA[256], sB[64], sC[128], sQ[256], sR[64];
    __shared__ float sCA[128], sCB[32], sCQ[128], sSR0[64];
    __shared__ float sP[256], sT1[256], sPp[256], sCT[128], sW[128], sK[128], sSm[64], sSi[64];

    const int tid = threadIdx.x;
    const int i  = tid >> 4;
    const int jc = tid & 15;

    sA[tid] = A[tid];
    sQ[tid] = Q[tid];
    if (tid < 64)  { sB[tid] = B[tid]; sR[tid] = R[tid]; }
    if (tid < 128) sC[tid] = C[tid];
    sP[tid] = (i == jc) ? 1.0f : 0.0f;   // P0 = I
    __syncthreads();

    if (tid < 128) {                      // CA = C*A, CQ = C*Q  (8x16)
        float a = 0.f, q = 0.f;
        int m = tid >> 4, jj = tid & 15;
        #pragma unroll
        for (int k = 0; k < 16; ++k) {
            a += sC[m * 16 + k] * sA[k * 16 + jj];
            q += sC[m * 16 + k] * sQ[k * 16 + jj];
        }
        sCA[tid] = a; sCQ[tid] = q;
    }
    if (tid < 32) {                       // CB = C*B  (8x4)
        float a = 0.f;
        #pragma unroll
        for (int k = 0; k < 16; ++k) a += sC[(tid >> 2) * 16 + k] * sB[k * 4 + (tid & 3)];
        sCB[tid] = a;
    }
    __syncthreads();
    if (tid < 64) {                       // SR0 = CQ*C^T + R (8x8)
        int m = tid >> 3, n = tid & 7;
        float s = sR[tid];
        #pragma unroll
        for (int k = 0; k < 16; ++k) s += sCQ[m * 16 + k] * sC[n * 16 + k];
        sSR0[tid] = s;
    }
    __syncthreads();

    int tconv = SEQ;
    for (int t = 1; t < SEQ; ++t) {
        // (1) T1 = A * P
        float a = 0.f;
        #pragma unroll
        for (int k = 0; k < 16; ++k) a += sA[i * 16 + k] * sP[k * 16 + jc];
        sT1[tid] = a;
        __syncthreads();
        // (2) Ppri = T1*A^T + Q (all)  ;  CT = C*T1 (tid<128)
        a = sQ[tid];
        #pragma unroll
        for (int k = 0; k < 16; ++k) a += sT1[i * 16 + k] * sA[jc * 16 + k];
        sPp[tid] = a;
        if (tid < 128) {
            int m = tid >> 4, jj = tid & 15;
            float w = 0.f;
            #pragma unroll
            for (int k = 0; k < 16; ++k) w += sC[m * 16 + k] * sT1[k * 16 + jj];
            sCT[tid] = w;
        }
        __syncthreads();
        // (3) W = CT*A^T + CQ (tid<128)  ;  S = CT*CA^T + SR0 (tid 128..191)
        if (tid < 128) {
            int m = tid >> 4, jj = tid & 15;
            float w = sCQ[tid];
            #pragma unroll
            for (int k = 0; k < 16; ++k) w += sCT[m * 16 + k] * sA[jj * 16 + k];
            sW[tid] = w;
        } else if (tid < 192) {
            int q = tid - 128, m = q >> 3, n = q & 7;
            float s = sSR0[q];
            #pragma unroll
            for (int k = 0; k < 16; ++k) s += sCT[m * 16 + k] * sCA[n * 16 + k];
            sSm[q] = s;
        }
        __syncthreads();
        // (4) Sinv: warp-synchronous Gauss-Jordan (8 lanes, SPD)
        if (tid < 8) {
            float row[16];
            #pragma unroll
            for (int c = 0; c < 8; ++c) { row[c] = sSm[tid * 8 + c]; row[c + 8] = (c == tid) ? 1.f : 0.f; }
            #pragma unroll
            for (int p = 0; p < 8; ++p) {
                float pv  = __shfl_sync(0xFFu, row[p], p, 8);
                float f   = row[p];
                float inv = 1.0f / pv;
                #pragma unroll
                for (int c = 0; c < 16; ++c) {
                    float pr = __shfl_sync(0xFFu, row[c], p, 8) * inv;
                    row[c] = (tid == p) ? pr : (row[c] - f * pr);
                }
            }
            #pragma unroll
            for (int c = 0; c < 8; ++c) sSi[tid * 8 + c] = row[c + 8];
        }
        __syncthreads();
        // (5) K = W^T * Sinv  (16x8)
        if (tid < 128) {
            int ii = tid >> 3, m = tid & 7;
            float kk = 0.f;
            #pragma unroll
            for (int n = 0; n < 8; ++n) kk += sW[n * 16 + ii] * sSi[n * 8 + m];
            sK[tid] = kk;
        }
        __syncthreads();
        // (6) outputs + Ppost + convergence
        {
            float mm = sA[tid];                         // M = A - K*CA
            #pragma unroll
            for (int m = 0; m < 8; ++m) mm -= sK[i * 8 + m] * sCA[m * 16 + jc];
            d_G2[(size_t)t * GQ + tid] = make_float2(mm, mm);
        }
        if (tid < 64) {                                 // N = B - K*CB
            int ii = tid >> 2, u = tid & 3;
            float nn = sB[tid];
            #pragma unroll
            for (int m = 0; m < 8; ++m) nn -= sK[ii * 8 + m] * sCB[m * 4 + u];
            d_G2[(size_t)t * GQ + 256 + tid] = make_float2(nn, nn);
        }
        if (tid < 128) {
            float kk = sK[tid];
            d_G2[(size_t)t * GQ + 320 + tid] = make_float2(kk, kk);
        }
        float pn = sPp[tid];                            // Ppost = Ppri - K*W
        #pragma unroll
        for (int m = 0; m < 8; ++m) pn -= sK[i * 8 + m] * sW[m * 16 + jc];
        int pred = fabsf(pn - sP[tid]) < 1e-5f;
        sP[tid] = pn;
        int conv = __syncthreads_and(pred);
        if (conv) { tconv = t + 1; break; }
    }
    __syncthreads();
    const int tlast = (tconv < SEQ) ? (tconv - 1) : (SEQ - 1);
    for (int q = tid; q < GQ; q += 256) d_Gst2[q] = d_G2[(size_t)tlast * GQ + q];
    if (tid == 0) d_tconv = tconv;
}

// =========================================================================
// Kernel 2: broadcast steady gains to t >= tconv
// =========================================================================
__global__ void fill_kernel()
{
    const int t = blockIdx.x + 1;        // 1..4095
    if (t < d_tconv) return;
    const int q = threadIdx.x;           // 224 threads * float4 = 448 float2
    reinterpret_cast<float4*>(&d_G2[(size_t)t * GQ])[q] =
        reinterpret_cast<const float4*>(d_Gst2)[q];
}

// =========================================================================
// Kernel 3: per-chunk transition matrices Phi_j (M scalars = .x of pairs)
// =========================================================================
__global__ void __launch_bounds__(256) phi_kernel()
{
    __shared__ float sPhi[256], sM[256];
    const int j = blockIdx.x, tid = threadIdx.x;
    const int i = tid >> 4, jc = tid & 15;
    const int t0 = j * LCH + 1;
    sPhi[tid] = d_G2[(size_t)t0 * GQ + tid].x;
    __syncthreads();
    for (int s = 1; s < LCH; ++s) {
        const int t = t0 + s;
        if (t >= SEQ) break;
        sM[tid] = d_G2[(size_t)t * GQ + tid].x;
        __syncthreads();
        float a = 0.f;
        #pragma unroll
        for (int k = 0; k < 16; ++k) a += sM[i * 16 + k] * sPhi[k * 16 + jc];
        __syncthreads();
        sPhi[tid] = a;
        __syncthreads();
    }
    d_Phi[j * 256 + tid] = sPhi[tid];
}

// =========================================================================
// Kernel 4: per-group transition matrices Psi_g = prod of 16 Phi
// =========================================================================
__global__ void __launch_bounds__(256) psi_kernel()
{
    __shared__ float sPsi[256], sM[256];
    const int g = blockIdx.x, tid = threadIdx.x;
    const int i = tid >> 4, jc = tid & 15;
    sPsi[tid] = d_Phi[(g * GRP) * 256 + tid];
    __syncthreads();
    for (int c = 1; c < GRP; ++c) {
        sM[tid] = d_Phi[(g * GRP + c) * 256 + tid];
        __syncthreads();
        float a = 0.f;
        #pragma unroll
        for (int k = 0; k < 16; ++k) a += sM[i * 16 + k] * sPsi[k * 16 + jc];
        __syncthreads();
        sPsi[tid] = a;
        __syncthreads();
    }
    d_Psi[g * 256 + tid] = sPsi[tid];
}

// =========================================================================
// packed affine step:  x <- M x + N u + K z   for a batch pair
// =========================================================================
__device__ __forceinline__ void kstep2(unsigned long long x[NS],
                                       const unsigned long long* __restrict__ g,
                                       const unsigned long long zz[MS],
                                       const unsigned long long uu[US])
{
    unsigned long long acc[NS];
    #pragma unroll
    for (int i = 0; i < NS; ++i) {
        const unsigned long long* gm = g + i * 16;
        const unsigned long long* gn = g + 256 + i * 4;
        const unsigned long long* gk = g + 320 + i * 8;
        unsigned long long a = fmul2(gn[0], uu[0]);
        a = ffma2(gn[1], uu[1], a);
        a = ffma2(gn[2], uu[2], a);
        a = ffma2(gn[3], uu[3], a);
        #pragma unroll
        for (int m = 0; m < MS; ++m) a = ffma2(gk[m], zz[m], a);
        #pragma unroll
        for (int k = 0; k < NS; ++k) a = ffma2(gm[k], x[k], a);
        acc[i] = a;
    }
    #pragma unroll
    for (int i = 0; i < NS; ++i) x[i] = acc[i];
}

__device__ __forceinline__ void load_zu2(const float* __restrict__ obs,
                                         const float* __restrict__ inp,
                                         int b0, int b1, int t,
                                         unsigned long long zz[MS], unsigned long long uu[US])
{
    const float4* z0p = reinterpret_cast<const float4*>(obs + ((size_t)b0 * SEQ + t) * MS);
    const float4* z1p = reinterpret_cast<const float4*>(obs + ((size_t)b1 * SEQ + t) * MS);
    float4 a0 = __ldg(z0p), a1 = __ldg(z0p + 1);
    float4 c0 = __ldg(z1p), c1 = __ldg(z1p + 1);
    zz[0] = pack2(a0.x, c0.x); zz[1] = pack2(a0.y, c0.y);
    zz[2] = pack2(a0.z, c0.z); zz[3] = pack2(a0.w, c0.w);
    zz[4] = pack2(a1.x, c1.x); zz[5] = pack2(a1.y, c1.y);
    zz[6] = pack2(a1.z, c1.z); zz[7] = pack2(a1.w, c1.w);
    float4 u0 = __ldg(reinterpret_cast<const float4*>(inp + ((size_t)b0 * SEQ + t) * US));
    float4 u1 = __ldg(reinterpret_cast<const float4*>(inp + ((size_t)b1 * SEQ + t) * US));
    uu[0] = pack2(u0.x, u1.x); uu[1] = pack2(u0.y, u1.y);
    uu[2] = pack2(u0.z, u1.z); uu[3] = pack2(u0.w, u1.w);
}

// =========================================================================
// Kernel 5: zero-start chunk responses (block = chunk, 128 thr x 2 batches)
// =========================================================================
__global__ void __launch_bounds__(128) vpass_kernel(const float* __restrict__ obs,
                                                    const float* __restrict__ inp)
{
    const int j = blockIdx.x, tid = threadIdx.x;
    const int b0 = tid, b1 = tid + 128;
    __shared__ __align__(16) unsigned long long gbuf[2][GQ];

    const int t0 = j * LCH + 1;
    const int steps = (t0 + LCH <= SEQ) ? LCH : (SEQ - t0);

    {   // prologue: stage gains for step 0
        const float4* src = reinterpret_cast<const float4*>(&d_G2[(size_t)t0 * GQ]);
        float4 r0 = __ldg(src + tid);
        reinterpret_cast<float4*>(gbuf[0])[tid] = r0;
        if (tid < 96) reinterpret_cast<float4*>(gbuf[0])[128 + tid] = __ldg(src + 128 + tid);
    }
    __syncthreads();

    unsigned long long x[NS];
    #pragma unroll
    for (int q = 0; q < NS; ++q) x[q] = 0ull;

    int p = 0;
    for (int s = 0; s < steps; ++s) {
        const int t = t0 + s;
        const bool more = (s + 1 < steps);
        float4 n0, n1;
        if (more) {
            const float4* nsrc = reinterpret_cast<const float4*>(&d_G2[(size_t)(t + 1) * GQ]);
            n0 = __ldg(nsrc + tid);
            if (tid < 96) n1 = __ldg(nsrc + 128 + tid);
        }
        unsigned long long zz[MS], uu[US];
        load_zu2(obs, inp, b0, b1, t, zz, uu);
        kstep2(x, gbuf[p], zz, uu);
        if (more) {
            reinterpret_cast<float4*>(gbuf[p ^ 1])[tid] = n0;
            if (tid < 96) reinterpret_cast<float4*>(gbuf[p ^ 1])[128 + tid] = n1;
        }
        __syncthreads();
        p ^= 1;
    }

    float lo[NS], hi[NS];
    #pragma unroll
    for (int q = 0; q < NS; ++q) unpk2(x[q], lo[q], hi[q]);
    float4* v0 = reinterpret_cast<float4*>(&d_V[((size_t)j * BATCH + b0) * NS]);
    float4* v1 = reinterpret_cast<float4*>(&d_V[((size_t)j * BATCH + b1) * NS]);
    v0[0] = make_float4(lo[0], lo[1], lo[2],  lo[3]);
    v0[1] = make_float4(lo[4], lo[5], lo[6],  lo[7]);
    v0[2] = make_float4(lo[8], lo[9], lo[10], lo[11]);
    v0[3] = make_float4(lo[12], lo[13], lo[14], lo[15]);
    v1[0] = make_float4(hi[0], hi[1], hi[2],  hi[3]);
    v1[1] = make_float4(hi[4], hi[5], hi[6],  hi[7]);
    v1[2] = make_float4(hi[8], hi[9], hi[10], hi[11]);
    v1[3] = make_float4(hi[12], hi[13], hi[14], hi[15]);
}

// ---------------- 16-lane shuffle matvec: a = v + P(row i) * s ----------------
__device__ __forceinline__ float affine16(const float* __restrict__ rowbase, float v, float s)
{
    const float4* pr = reinterpret_cast<const float4*>(rowbase);
    float4 p0 = __ldg(pr), p1 = __ldg(pr + 1), p2 = __ldg(pr + 2), p3 = __ldg(pr + 3);
    float a = v;
    a += p0.x * __shfl_sync(0xFFFFFFFFu, s, 0, 16)  + p0.y * __shfl_sync(0xFFFFFFFFu, s, 1, 16)
       + p0.z * __shfl_sync(0xFFFFFFFFu, s, 2, 16)  + p0.w * __shfl_sync(0xFFFFFFFFu, s, 3, 16);
    a += p1.x * __shfl_sync(0xFFFFFFFFu, s, 4, 16)  + p1.y * __shfl_sync(0xFFFFFFFFu, s, 5, 16)
       + p1.z * __shfl_sync(0xFFFFFFFFu, s, 6, 16)  + p1.w * __shfl_sync(0xFFFFFFFFu, s, 7, 16);
    a += p2.x * __shfl_sync(0xFFFFFFFFu, s, 8, 16)  + p2.y * __shfl_sync(0xFFFFFFFFu, s, 9, 16)
       + p2.z * __shfl_sync(0xFFFFFFFFu, s, 10, 16) + p2.w * __shfl_sync(0xFFFFFFFFu, s, 11, 16);
    a += p3.x * __shfl_sync(0xFFFFFFFFu, s, 12, 16) + p3.y * __shfl_sync(0xFFFFFFFFu, s, 13, 16)
       + p3.z * __shfl_sync(0xFFFFFFFFu, s, 14, 16) + p3.w * __shfl_sync(0xFFFFFFFFu, s, 15, 16);
    return a;
}

// =========================================================================
// Kernel 6a: group zero-responses GV_g (scan 16 chunks from zero)
// =========================================================================
__global__ void __launch_bounds__(256) gscanA_kernel()
{
    const int g = blockIdx.x >> 4, sub = blockIdx.x & 15;
    const int tid = threadIdx.x;
    const int b = sub * 16 + (tid >> 4);
    const int i = tid & 15;
    float s = 0.f;
    for (int c = 0; c < GRP; ++c) {
        const int ch = g * GRP + c;
        float v = __ldg(&d_V[((size_t)ch * BATCH + b) * NS + i]);
        s = affine16(&d_Phi[ch * 256 + i * 16], v, s);
    }
    d_GV[((size_t)g * BATCH + b) * NS + i] = s;
}

// =========================================================================
// Kernel 6b: serial scan over 32 groups -> group start states GS_g
// =========================================================================
__global__ void __launch_bounds__(256) gscanB_kernel(const float* __restrict__ x0)
{
    const int tid = threadIdx.x;
    const int b = blockIdx.x * 16 + (tid >> 4);
    const int i = tid & 15;
    float s = __ldg(x0 + i);
    for (int g = 0; g < NGRP; ++g) {
        d_GS[((size_t)g * BATCH + b) * NS + i] = s;
        float v = __ldg(&d_GV[((size_t)g * BATCH + b) * NS + i]);
        s = affine16(&d_Psi[g * 256 + i * 16], v, s);
    }
}

// =========================================================================
// Kernel 6c: within-group chunk start states -> d_Sst
// =========================================================================
__global__ void __launch_bounds__(256) gscanC_kernel()
{
    const int g = blockIdx.x >> 4, sub = blockIdx.x & 15;
    const int tid = threadIdx.x;
    const int b = sub * 16 + (tid >> 4);
    const int i = tid & 15;
    float s = __ldg(&d_GS[((size_t)g * BATCH + b) * NS + i]);
    for (int c = 0; c < GRP; ++c) {
        const int ch = g * GRP + c;
        d_Sst[((size_t)ch * BATCH + b) * NS + i] = s;
        float v = __ldg(&d_V[((size_t)ch * BATCH + b) * NS + i]);
        s = affine16(&d_Phi[ch * 256 + i * 16], v, s);
    }
}

// =========================================================================
// Kernel 7: final pass — rerun chunk from true start, emit outputs
// =========================================================================
__global__ void __launch_bounds__(128) outpass_kernel(const float* __restrict__ obs,
                                                      const float* __restrict__ inp,
                                                      float* __restrict__ out)
{
    const int j = blockIdx.x, tid = threadIdx.x;
    const int b0 = tid, b1 = tid + 128;
    __shared__ __align__(16) unsigned long long gbuf[2][GQ];

    const int t0 = j * LCH + 1;
    const int steps = (t0 + LCH <= SEQ) ? LCH : (SEQ - t0);

    {
        const float4* src = reinterpret_cast<const float4*>(&d_G2[(size_t)t0 * GQ]);
        float4 r0 = __ldg(src + tid);
        reinterpret_cast<float4*>(gbuf[0])[tid] = r0;
        if (tid < 96) reinterpret_cast<float4*>(gbuf[0])[128 + tid] = __ldg(src + 128 + tid);
    }

    unsigned long long x[NS];
    {
        const float4* s0 = reinterpret_cast<const float4*>(&d_Sst[((size_t)j * BATCH + b0) * NS]);
        const float4* s1 = reinterpret_cast<const float4*>(&d_Sst[((size_t)j * BATCH + b1) * NS]);
        float4 q0 = __ldg(s0), q1 = __ldg(s0 + 1), q2 = __ldg(s0 + 2), q3 = __ldg(s0 + 3);
        float4 r0 = __ldg(s1), r1 = __ldg(s1 + 1), r2 = __ldg(s1 + 2), r3 = __ldg(s1 + 3);
        x[0]  = pack2(q0.x, r0.x); x[1]  = pack2(q0.y, r0.y); x[2]  = pack2(q0.z, r0.z); x[3]  = pack2(q0.w, r0.w);
        x[4]  = pack2(q1.x, r1.x); x[5]  = pack2(q1.y, r1.y); x[6]  = pack2(q1.z, r1.z); x[7]  = pack2(q1.w, r1.w);
        x[8]  = pack2(q2.x, r2.x); x[9]  = pack2(q2.y, r2.y); x[10] = pack2(q2.z, r2.z); x[11] = pack2(q2.w, r2.w);
        x[12] = pack2(q3.x, r3.x); x[13] = pack2(q3.y, r3.y); x[14] = pack2(q3.z, r3.z); x[15] = pack2(q3.w, r3.w);
    }
    __syncthreads();

    if (j == 0) {      // out[b][0] = x0 = chunk-0 start state
        float lo[NS], hi[NS];
        #pragma unroll
        for (int q = 0; q < NS; ++q) unpk2(x[q], lo[q], hi[q]);
        float4* o0 = reinterpret_cast<float4*>(out + (size_t)b0 * SEQ * NS);
        float4* o1 = reinterpret_cast<float4*>(out + (size_t)b1 * SEQ * NS);
        o0[0] = make_float4(lo[0], lo[1], lo[2],  lo[3]);
        o0[1] = make_float4(lo[4], lo[5], lo[6],  lo[7]);
        o0[2] = make_float4(lo[8], lo[9], lo[10], lo[11]);
        o0[3] = make_float4(lo[12], lo[13], lo[14], lo[15]);
        o1[0] = make_float4(hi[0], hi[1], hi[2],  hi[3]);
        o1[1] = make_float4(hi[4], hi[5], hi[6],  hi[7]);
        o1[2] = make_float4(hi[8], hi[9], hi[10], hi[11]);
        o1[3] = make_float4(hi[12], hi[13], hi[14], hi[15]);
    }

    int p = 0;
    for (int s = 0; s < steps; ++s) {
        const int t = t0 + s;
        const bool more = (s + 1 < steps);
        float4 n0, n1;
        if (more) {
            const float4* nsrc = reinterpret_cast<const float4*>(&d_G2[(size_t)(t + 1) * GQ]);
            n0 = __ldg(nsrc + tid);
            if (tid < 96) n1 = __ldg(nsrc + 128 + tid);
        }
        unsigned long long zz[MS], uu[US];
        load_zu2(obs, inp, b0, b1, t, zz, uu);
        kstep2(x, gbuf[p], zz, uu);
        if (more) {
            reinterpret_cast<float4*>(gbuf[p ^ 1])[tid] = n0;
            if (tid < 96) reinterpret_cast<float4*>(gbuf[p ^ 1])[128 + tid] = n1;
        }
        float lo[NS], hi[NS];
        #pragma unroll
        for (int q = 0; q < NS; ++q) unpk2(x[q], lo[q], hi[q]);
        float4* o0 = reinterpret_cast<float4*>(out + ((size_t)b0 * SEQ + t) * NS);
        float4* o1 = reinterpret_cast<float4*>(out + ((size_t)b1 * SEQ + t) * NS);
        o0[0] = make_float4(lo[0], lo[1], lo[2],  lo[3]);
        o0[1] = make_float4(lo[4], lo[5], lo[6],  lo[7]);
        o0[2] = make_float4(lo[8], lo[9], lo[10], lo[11]);
        o0[3] = make_float4(lo[12], lo[13], lo[14], lo[15]);
        o1[0] = make_float4(hi[0], hi[1], hi[2],  hi[3]);
        o1[1] = make_float4(hi[4], hi[5], hi[6],  hi[7]);
        o1[2] = make_float4(hi[8], hi[9], hi[10], hi[11]);
        o1[3] = make_float4(hi[12], hi[13], hi[14], hi[15]);
        __syncthreads();
        p ^= 1;
    }
}

// =========================================================================
extern "C" void kernel_launch(void* const* d_in, const int* in_sizes, int n_in,
                              void* d_out, int out_size)
{
    (void)in_sizes; (void)n_in; (void)out_size;
    const float* obs = (const float*)d_in[0];
    const float* inp = (const float*)d_in[1];
    const float* A   = (const float*)d_in[2];
    const float* B   = (const float*)d_in[3];
    const float* C   = (const float*)d_in[4];
    const float* Q   = (const float*)d_in[5];
    const float* R   = (const float*)d_in[6];
    const float* x0  = (const float*)d_in[7];
    float* out = (float*)d_out;

    riccati_kernel<<<1, 256>>>(A, B, C, Q, R);
    fill_kernel<<<SEQ - 1, 224>>>();
    phi_kernel<<<NCH, 256>>>();
    psi_kernel<<<NGRP, 256>>>();
    vpass_kernel<<<NCH, 128>>>(obs, inp);
    gscanA_kernel<<<NGRP * 16, 256>>>();
    gscanB_kernel<<<BATCH / 16, 256>>>(x0);
    gscanC_kernel<<<NGRP * 16, 256>>>();
    outpass_kernel<<<NCH, 128>>>(obs, inp, out);
}

// round 8
// speedup vs baseline: 1.0464x; 1.0004x over previous
#include <cuda_runtime.h>
#include <cstdint>
#include <cstddef>

#define SEQ   4096
#define BATCH 256
#define NS    16
#define MS    8
#define US    4
#define LCH   8           // chunk length
#define NCH   512         // chunks
#define GRP   16          // chunks per group
#define NGRP  32          // groups
#define GQ    448         // gain scalars per t: M(256)|N(64)|K(128)

// ---------------- device scratch ----------------
__device__ __align__(16) float2 d_G2[(size_t)SEQ * GQ];   // duplicated (g,g) pairs
__device__ __align__(16) float2 d_Gst2[GQ];
__device__ int d_tconv;
__device__ __align__(16) float d_Phi[NCH * 256];
__device__ __align__(16) float d_Psi[NGRP * 256];
__device__ __align__(16) float d_V  [(size_t)NCH  * BATCH * NS];
__device__ __align__(16) float d_GV [(size_t)NGRP * BATCH * NS];
__device__ __align__(16) float d_GS [(size_t)NGRP * BATCH * NS];
__device__ __align__(16) float d_Sst[(size_t)NCH  * BATCH * NS];

// ---------------- f32x2 helpers ----------------
__device__ __forceinline__ unsigned long long ffma2(unsigned long long a, unsigned long long b, unsigned long long c) {
    unsigned long long d;
    asm("fma.rn.f32x2 %0, %1, %2, %3;" : "=l"(d) : "l"(a), "l"(b), "l"(c));
    return d;
}
__device__ __forceinline__ unsigned long long fmul2(unsigned long long a, unsigned long long b) {
    unsigned long long d;
    asm("mul.rn.f32x2 %0, %1, %2;" : "=l"(d) : "l"(a), "l"(b));
    return d;
}
__device__ __forceinline__ unsigned long long pack2(float x, float y) {
    unsigned long long r;
    asm("mov.b64 %0, {%1, %2};" : "=l"(r) : "f"(x), "f"(y));
    return r;
}
__device__ __forceinline__ void unpk2(unsigned long long v, float& lo, float& hi) {
    asm("mov.b64 {%0, %1}, %2;" : "=f"(lo), "=f"(hi) : "l"(v));
}

// =========================================================================
// Kernel 1: serial Riccati recursion (one block), 6 barriers/step
// =========================================================================
__global__ void __launch_bounds__(256) riccati_kernel(
    const float* __restrict__ A, const float* __restrict__ B,
    const float* __restrict__ C, const float* __restrict__ Q,
    const float* __restrict__ R)
{
    __shared__ float sA[256], sB[64], sC[128], sQ[256], sR[64];
    __shared__ float sCA[128], sCB[32], sCQ[128], sSR0[64];
    __shared__ float sP[256], sT1[256], sPp[256], sCT[128], sW[128], sK[128], sSm[64], sSi[64];

    const int tid = threadIdx.x;
    const int i  = tid >> 4;
    const int jc = tid & 15;

    sA[tid] = A[tid];
    sQ[tid] = Q[tid];
    if (tid < 64)  { sB[tid] = B[tid]; sR[tid] = R[tid]; }
    if (tid < 128) sC[tid] = C[tid];
    sP[tid] = (i == jc) ? 1.0f : 0.0f;   // P0 = I
    __syncthreads();

    if (tid < 128) {                      // CA = C*A, CQ = C*Q  (8x16)
        float a = 0.f, q = 0.f;
        int m = tid >> 4, jj = tid & 15;
        #pragma unroll
        for (int k = 0; k < 16; ++k) {
            a += sC[m * 16 + k] * sA[k * 16 + jj];
            q += sC[m * 16 + k] * sQ[k * 16 + jj];
        }
        sCA[tid] = a; sCQ[tid] = q;
    }
    if (tid < 32) {                       // CB = C*B  (8x4)
        float a = 0.f;
        #pragma unroll
        for (int k = 0; k < 16; ++k) a += sC[(tid >> 2) * 16 + k] * sB[k * 4 + (tid & 3)];
        sCB[tid] = a;
    }
    __syncthreads();
    if (tid < 64) {                       // SR0 = CQ*C^T + R (8x8)
        int m = tid >> 3, n = tid & 7;
        float s = sR[tid];
        #pragma unroll
        for (int k = 0; k < 16; ++k) s += sCQ[m * 16 + k] * sC[n * 16 + k];
        sSR0[tid] = s;
    }
    __syncthreads();

    int tconv = SEQ;
    for (int t = 1; t < SEQ; ++t) {
        // (1) T1 = A * P
        float a = 0.f;
        #pragma unroll
        for (int k = 0; k < 16; ++k) a += sA[i * 16 + k] * sP[k * 16 + jc];
        sT1[tid] = a;
        __syncthreads();
        // (2) Ppri = T1*A^T + Q (all)  ;  CT = C*T1 (tid<128)
        a = sQ[tid];
        #pragma unroll
        for (int k = 0; k < 16; ++k) a += sT1[i * 16 + k] * sA[jc * 16 + k];
        sPp[tid] = a;
        if (tid < 128) {
            int m = tid >> 4, jj = tid & 15;
            float w = 0.f;
            #pragma unroll
            for (int k = 0; k < 16; ++k) w += sC[m * 16 + k] * sT1[k * 16 + jj];
            sCT[tid] = w;
        }
        __syncthreads();
        // (3) W = CT*A^T + CQ (tid<128)  ;  S = CT*CA^T + SR0 (tid 128..191)
        if (tid < 128) {
            int m = tid >> 4, jj = tid & 15;
            float w = sCQ[tid];
            #pragma unroll
            for (int k = 0; k < 16; ++k) w += sCT[m * 16 + k] * sA[jj * 16 + k];
            sW[tid] = w;
        } else if (tid < 192) {
            int q = tid - 128, m = q >> 3, n = q & 7;
            float s = sSR0[q];
            #pragma unroll
            for (int k = 0; k < 16; ++k) s += sCT[m * 16 + k] * sCA[n * 16 + k];
            sSm[q] = s;
        }
        __syncthreads();
        // (4) Sinv: warp-synchronous Gauss-Jordan (8 lanes, SPD)
        if (tid < 8) {
            float row[16];
            #pragma unroll
            for (int c = 0; c < 8; ++c) { row[c] = sSm[tid * 8 + c]; row[c + 8] = (c == tid) ? 1.f : 0.f; }
            #pragma unroll
            for (int p = 0; p < 8; ++p) {
                float pv  = __shfl_sync(0xFFu, row[p], p, 8);
                float f   = row[p];
                float inv = 1.0f / pv;
                #pragma unroll
                for (int c = 0; c < 16; ++c) {
                    float pr = __shfl_sync(0xFFu, row[c], p, 8) * inv;
                    row[c] = (tid == p) ? pr : (row[c] - f * pr);
                }
            }
            #pragma unroll
            for (int c = 0; c < 8; ++c) sSi[tid * 8 + c] = row[c + 8];
        }
        __syncthreads();
        // (5) K = W^T * Sinv  (16x8)
        if (tid < 128) {
            int ii = tid >> 3, m = tid & 7;
            float kk = 0.f;
            #pragma unroll
            for (int n = 0; n < 8; ++n) kk += sW[n * 16 + ii] * sSi[n * 8 + m];
            sK[tid] = kk;
        }
        __syncthreads();
        // (6) outputs + Ppost + convergence
        {
            float mm = sA[tid];                         // M = A - K*CA
            #pragma unroll
            for (int m = 0; m < 8; ++m) mm -= sK[i * 8 + m] * sCA[m * 16 + jc];
            d_G2[(size_t)t * GQ + tid] = make_float2(mm, mm);
        }
        if (tid < 64) {                                 // N = B - K*CB
            int ii = tid >> 2, u = tid & 3;
            float nn = sB[tid];
            #pragma unroll
            for (int m = 0; m < 8; ++m) nn -= sK[ii * 8 + m] * sCB[m * 4 + u];
            d_G2[(size_t)t * GQ + 256 + tid] = make_float2(nn, nn);
        }
        if (tid < 128) {
            float kk = sK[tid];
            d_G2[(size_t)t * GQ + 320 + tid] = make_float2(kk, kk);
        }
        float pn = sPp[tid];                            // Ppost = Ppri - K*W
        #pragma unroll
        for (int m = 0; m < 8; ++m) pn -= sK[i * 8 + m] * sW[m * 16 + jc];
        int pred = fabsf(pn - sP[tid]) < 1e-5f;
        sP[tid] = pn;
        int conv = __syncthreads_and(pred);
        if (conv) { tconv = t + 1; break; }
    }
    __syncthreads();
    const int tlast = (tconv < SEQ) ? (tconv - 1) : (SEQ - 1);
    for (int q = tid; q < GQ; q += 256) d_Gst2[q] = d_G2[(size_t)tlast * GQ + q];
    if (tid == 0) d_tconv = tconv;
}

// =========================================================================
// Kernel 2: broadcast steady gains to t >= tconv
// =========================================================================
__global__ void fill_kernel()
{
    const int t = blockIdx.x + 1;        // 1..4095
    if (t < d_tconv) return;
    const int q = threadIdx.x;           // 224 threads * float4 = 448 float2
    reinterpret_cast<float4*>(&d_G2[(size_t)t * GQ])[q] =
        reinterpret_cast<const float4*>(d_Gst2)[q];
}

// =========================================================================
// Kernel 3: per-chunk transition matrices Phi_j (M scalars = .x of pairs)
// =========================================================================
__global__ void __launch_bounds__(256) phi_kernel()
{
    __shared__ float sPhi[256], sM[256];
    const int j = blockIdx.x, tid = threadIdx.x;
    const int i = tid >> 4, jc = tid & 15;
    const int t0 = j * LCH + 1;
    sPhi[tid] = d_G2[(size_t)t0 * GQ + tid].x;
    __syncthreads();
    for (int s = 1; s < LCH; ++s) {
        const int t = t0 + s;
        if (t >= SEQ) break;
        sM[tid] = d_G2[(size_t)t * GQ + tid].x;
        __syncthreads();
        float a = 0.f;
        #pragma unroll
        for (int k = 0; k < 16; ++k) a += sM[i * 16 + k] * sPhi[k * 16 + jc];
        __syncthreads();
        sPhi[tid] = a;
        __syncthreads();
    }
    d_Phi[j * 256 + tid] = sPhi[tid];
}

// =========================================================================
// Kernel 4: per-group transition matrices Psi_g = prod of 16 Phi
// =========================================================================
__global__ void __launch_bounds__(256) psi_kernel()
{
    __shared__ float sPsi[256], sM[256];
    const int g = blockIdx.x, tid = threadIdx.x;
    const int i = tid >> 4, jc = tid & 15;
    sPsi[tid] = d_Phi[(g * GRP) * 256 + tid];
    __syncthreads();
    for (int c = 1; c < GRP; ++c) {
        sM[tid] = d_Phi[(g * GRP + c) * 256 + tid];
        __syncthreads();
        float a = 0.f;
        #pragma unroll
        for (int k = 0; k < 16; ++k) a += sM[i * 16 + k] * sPsi[k * 16 + jc];
        __syncthreads();
        sPsi[tid] = a;
        __syncthreads();
    }
    d_Psi[g * 256 + tid] = sPsi[tid];
}

// =========================================================================
// packed affine step:  x <- M x + N u + K z   for a batch pair
// =========================================================================
__device__ __forceinline__ void kstep2(unsigned long long x[NS],
                                       const unsigned long long* __restrict__ g,
                                       const unsigned long long zz[MS],
                                       const unsigned long long uu[US])
{
    unsigned long long acc[NS];
    #pragma unroll
    for (int i = 0; i < NS; ++i) {
        const unsigned long long* gm = g + i * 16;
        const unsigned long long* gn = g + 256 + i * 4;
        const unsigned long long* gk = g + 320 + i * 8;
        unsigned long long a = fmul2(gn[0], uu[0]);
        a = ffma2(gn[1], uu[1], a);
        a = ffma2(gn[2], uu[2], a);
        a = ffma2(gn[3], uu[3], a);
        #pragma unroll
        for (int m = 0; m < MS; ++m) a = ffma2(gk[m], zz[m], a);
        #pragma unroll
        for (int k = 0; k < NS; ++k) a = ffma2(gm[k], x[k], a);
        acc[i] = a;
    }
    #pragma unroll
    for (int i = 0; i < NS; ++i) x[i] = acc[i];
}

__device__ __forceinline__ void load_zu2(const float* __restrict__ obs,
                                         const float* __restrict__ inp,
                                         int b0, int b1, int t,
                                         unsigned long long zz[MS], unsigned long long uu[US])
{
    const float4* z0p = reinterpret_cast<const float4*>(obs + ((size_t)b0 * SEQ + t) * MS);
    const float4* z1p = reinterpret_cast<const float4*>(obs + ((size_t)b1 * SEQ + t) * MS);
    float4 a0 = __ldg(z0p), a1 = __ldg(z0p + 1);
    float4 c0 = __ldg(z1p), c1 = __ldg(z1p + 1);
    zz[0] = pack2(a0.x, c0.x); zz[1] = pack2(a0.y, c0.y);
    zz[2] = pack2(a0.z, c0.z); zz[3] = pack2(a0.w, c0.w);
    zz[4] = pack2(a1.x, c1.x); zz[5] = pack2(a1.y, c1.y);
    zz[6] = pack2(a1.z, c1.z); zz[7] = pack2(a1.w, c1.w);
    float4 u0 = __ldg(reinterpret_cast<const float4*>(inp + ((size_t)b0 * SEQ + t) * US));
    float4 u1 = __ldg(reinterpret_cast<const float4*>(inp + ((size_t)b1 * SEQ + t) * US));
    uu[0] = pack2(u0.x, u1.x); uu[1] = pack2(u0.y, u1.y);
    uu[2] = pack2(u0.z, u1.z); uu[3] = pack2(u0.w, u1.w);
}

// =========================================================================
// Kernel 5: zero-start chunk responses (block = chunk, 128 thr x 2 batches)
// =========================================================================
__global__ void __launch_bounds__(128) vpass_kernel(const float* __restrict__ obs,
                                                    const float* __restrict__ inp)
{
    const int j = blockIdx.x, tid = threadIdx.x;
    const int b0 = tid, b1 = tid + 128;
    __shared__ __align__(16) unsigned long long gbuf[2][GQ];

    const int t0 = j * LCH + 1;
    const int steps = (t0 + LCH <= SEQ) ? LCH : (SEQ - t0);

    {   // prologue: stage gains for step 0
        const float4* src = reinterpret_cast<const float4*>(&d_G2[(size_t)t0 * GQ]);
        float4 r0 = __ldg(src + tid);
        reinterpret_cast<float4*>(gbuf[0])[tid] = r0;
        if (tid < 96) reinterpret_cast<float4*>(gbuf[0])[128 + tid] = __ldg(src + 128 + tid);
    }
    __syncthreads();

    unsigned long long x[NS];
    #pragma unroll
    for (int q = 0; q < NS; ++q) x[q] = 0ull;

    int p = 0;
    for (int s = 0; s < steps; ++s) {
        const int t = t0 + s;
        const bool more = (s + 1 < steps);
        float4 n0, n1;
        if (more) {
            const float4* nsrc = reinterpret_cast<const float4*>(&d_G2[(size_t)(t + 1) * GQ]);
            n0 = __ldg(nsrc + tid);
            if (tid < 96) n1 = __ldg(nsrc + 128 + tid);
        }
        unsigned long long zz[MS], uu[US];
        load_zu2(obs, inp, b0, b1, t, zz, uu);
        kstep2(x, gbuf[p], zz, uu);
        if (more) {
            reinterpret_cast<float4*>(gbuf[p ^ 1])[tid] = n0;
            if (tid < 96) reinterpret_cast<float4*>(gbuf[p ^ 1])[128 + tid] = n1;
        }
        __syncthreads();
        p ^= 1;
    }

    float lo[NS], hi[NS];
    #pragma unroll
    for (int q = 0; q < NS; ++q) unpk2(x[q], lo[q], hi[q]);
    float4* v0 = reinterpret_cast<float4*>(&d_V[((size_t)j * BATCH + b0) * NS]);
    float4* v1 = reinterpret_cast<float4*>(&d_V[((size_t)j * BATCH + b1) * NS]);
    v0[0] = make_float4(lo[0], lo[1], lo[2],  lo[3]);
    v0[1] = make_float4(lo[4], lo[5], lo[6],  lo[7]);
    v0[2] = make_float4(lo[8], lo[9], lo[10], lo[11]);
    v0[3] = make_float4(lo[12], lo[13], lo[14], lo[15]);
    v1[0] = make_float4(hi[0], hi[1], hi[2],  hi[3]);
    v1[1] = make_float4(hi[4], hi[5], hi[6],  hi[7]);
    v1[2] = make_float4(hi[8], hi[9], hi[10], hi[11]);
    v1[3] = make_float4(hi[12], hi[13], hi[14], hi[15]);
}

// ---------------- 16-lane shuffle matvec: a = v + P(row i) * s ----------------
__device__ __forceinline__ float affine16(const float* __restrict__ rowbase, float v, float s)
{
    const float4* pr = reinterpret_cast<const float4*>(rowbase);
    float4 p0 = __ldg(pr), p1 = __ldg(pr + 1), p2 = __ldg(pr + 2), p3 = __ldg(pr + 3);
    float a = v;
    a += p0.x * __shfl_sync(0xFFFFFFFFu, s, 0, 16)  + p0.y * __shfl_sync(0xFFFFFFFFu, s, 1, 16)
       + p0.z * __shfl_sync(0xFFFFFFFFu, s, 2, 16)  + p0.w * __shfl_sync(0xFFFFFFFFu, s, 3, 16);
    a += p1.x * __shfl_sync(0xFFFFFFFFu, s, 4, 16)  + p1.y * __shfl_sync(0xFFFFFFFFu, s, 5, 16)
       + p1.z * __shfl_sync(0xFFFFFFFFu, s, 6, 16)  + p1.w * __shfl_sync(0xFFFFFFFFu, s, 7, 16);
    a += p2.x * __shfl_sync(0xFFFFFFFFu, s, 8, 16)  + p2.y * __shfl_sync(0xFFFFFFFFu, s, 9, 16)
       + p2.z * __shfl_sync(0xFFFFFFFFu, s, 10, 16) + p2.w * __shfl_sync(0xFFFFFFFFu, s, 11, 16);
    a += p3.x * __shfl_sync(0xFFFFFFFFu, s, 12, 16) + p3.y * __shfl_sync(0xFFFFFFFFu, s, 13, 16)
       + p3.z * __shfl_sync(0xFFFFFFFFu, s, 14, 16) + p3.w * __shfl_sync(0xFFFFFFFFu, s, 15, 16);
    return a;
}

// =========================================================================
// Kernel 6a: group zero-responses GV_g (scan 16 chunks from zero)
// =========================================================================
__global__ void __launch_bounds__(256) gscanA_kernel()
{
    const int g = blockIdx.x >> 4, sub = blockIdx.x & 15;
    const int tid = threadIdx.x;
    const int b = sub * 16 + (tid >> 4);
    const int i = tid & 15;
    float s = 0.f;
    for (int c = 0; c < GRP; ++c) {
        const int ch = g * GRP + c;
        float v = __ldg(&d_V[((size_t)ch * BATCH + b) * NS + i]);
        s = affine16(&d_Phi[ch * 256 + i * 16], v, s);
    }
    d_GV[((size_t)g * BATCH + b) * NS + i] = s;
}

// =========================================================================
// Kernel 6b: serial scan over 32 groups -> group start states GS_g
// =========================================================================
__global__ void __launch_bounds__(256) gscanB_kernel(const float* __restrict__ x0)
{
    const int tid = threadIdx.x;
    const int b = blockIdx.x * 16 + (tid >> 4);
    const int i = tid & 15;
    float s = __ldg(x0 + i);
    for (int g = 0; g < NGRP; ++g) {
        d_GS[((size_t)g * BATCH + b) * NS + i] = s;
        float v = __ldg(&d_GV[((size_t)g * BATCH + b) * NS + i]);
        s = affine16(&d_Psi[g * 256 + i * 16], v, s);
    }
}

// =========================================================================
// Kernel 6c: within-group chunk start states -> d_Sst
// =========================================================================
__global__ void __launch_bounds__(256) gscanC_kernel()
{
    const int g = blockIdx.x >> 4, sub = blockIdx.x & 15;
    const int tid = threadIdx.x;
    const int b = sub * 16 + (tid >> 4);
    const int i = tid & 15;
    float s = __ldg(&d_GS[((size_t)g * BATCH + b) * NS + i]);
    for (int c = 0; c < GRP; ++c) {
        const int ch = g * GRP + c;
        d_Sst[((size_t)ch * BATCH + b) * NS + i] = s;
        float v = __ldg(&d_V[((size_t)ch * BATCH + b) * NS + i]);
        s = affine16(&d_Phi[ch * 256 + i * 16], v, s);
    }
}

// =========================================================================
// Kernel 7: final pass — rerun chunk from true start, emit outputs
// =========================================================================
__global__ void __launch_bounds__(128) outpass_kernel(const float* __restrict__ obs,
                                                      const float* __restrict__ inp,
                                                      float* __restrict__ out)
{
    const int j = blockIdx.x, tid = threadIdx.x;
    const int b0 = tid, b1 = tid + 128;
    __shared__ __align__(16) unsigned long long gbuf[2][GQ];

    const int t0 = j * LCH + 1;
    const int steps = (t0 + LCH <= SEQ) ? LCH : (SEQ - t0);

    {
        const float4* src = reinterpret_cast<const float4*>(&d_G2[(size_t)t0 * GQ]);
        float4 r0 = __ldg(src + tid);
        reinterpret_cast<float4*>(gbuf[0])[tid] = r0;
        if (tid < 96) reinterpret_cast<float4*>(gbuf[0])[128 + tid] = __ldg(src + 128 + tid);
    }

    unsigned long long x[NS];
    {
        const float4* s0 = reinterpret_cast<const float4*>(&d_Sst[((size_t)j * BATCH + b0) * NS]);
        const float4* s1 = reinterpret_cast<const float4*>(&d_Sst[((size_t)j * BATCH + b1) * NS]);
        float4 q0 = __ldg(s0), q1 = __ldg(s0 + 1), q2 = __ldg(s0 + 2), q3 = __ldg(s0 + 3);
        float4 r0 = __ldg(s1), r1 = __ldg(s1 + 1), r2 = __ldg(s1 + 2), r3 = __ldg(s1 + 3);
        x[0]  = pack2(q0.x, r0.x); x[1]  = pack2(q0.y, r0.y); x[2]  = pack2(q0.z, r0.z); x[3]  = pack2(q0.w, r0.w);
        x[4]  = pack2(q1.x, r1.x); x[5]  = pack2(q1.y, r1.y); x[6]  = pack2(q1.z, r1.z); x[7]  = pack2(q1.w, r1.w);
        x[8]  = pack2(q2.x, r2.x); x[9]  = pack2(q2.y, r2.y); x[10] = pack2(q2.z, r2.z); x[11] = pack2(q2.w, r2.w);
        x[12] = pack2(q3.x, r3.x); x[13] = pack2(q3.y, r3.y); x[14] = pack2(q3.z, r3.z); x[15] = pack2(q3.w, r3.w);
    }
    __syncthreads();

    if (j == 0) {      // out[b][0] = x0 = chunk-0 start state
        float lo[NS], hi[NS];
        #pragma unroll
        for (int q = 0; q < NS; ++q) unpk2(x[q], lo[q], hi[q]);
        float4* o0 = reinterpret_cast<float4*>(out + (size_t)b0 * SEQ * NS);
        float4* o1 = reinterpret_cast<float4*>(out + (size_t)b1 * SEQ * NS);
        o0[0] = make_float4(lo[0], lo[1], lo[2],  lo[3]);
        o0[1] = make_float4(lo[4], lo[5], lo[6],  lo[7]);
        o0[2] = make_float4(lo[8], lo[9], lo[10], lo[11]);
        o0[3] = make_float4(lo[12], lo[13], lo[14], lo[15]);
        o1[0] = make_float4(hi[0], hi[1], hi[2],  hi[3]);
        o1[1] = make_float4(hi[4], hi[5], hi[6],  hi[7]);
        o1[2] = make_float4(hi[8], hi[9], hi[10], hi[11]);
        o1[3] = make_float4(hi[12], hi[13], hi[14], hi[15]);
    }

    int p = 0;
    for (int s = 0; s < steps; ++s) {
        const int t = t0 + s;
        const bool more = (s + 1 < steps);
        float4 n0, n1;
        if (more) {
            const float4* nsrc = reinterpret_cast<const float4*>(&d_G2[(size_t)(t + 1) * GQ]);
            n0 = __ldg(nsrc + tid);
            if (tid < 96) n1 = __ldg(nsrc + 128 + tid);
        }
        unsigned long long zz[MS], uu[US];
        load_zu2(obs, inp, b0, b1, t, zz, uu);
        kstep2(x, gbuf[p], zz, uu);
        if (more) {
            reinterpret_cast<float4*>(gbuf[p ^ 1])[tid] = n0;
            if (tid < 96) reinterpret_cast<float4*>(gbuf[p ^ 1])[128 + tid] = n1;
        }
        float lo[NS], hi[NS];
        #pragma unroll
        for (int q = 0; q < NS; ++q) unpk2(x[q], lo[q], hi[q]);
        float4* o0 = reinterpret_cast<float4*>(out + ((size_t)b0 * SEQ + t) * NS);
        float4* o1 = reinterpret_cast<float4*>(out + ((size_t)b1 * SEQ + t) * NS);
        o0[0] = make_float4(lo[0], lo[1], lo[2],  lo[3]);
        o0[1] = make_float4(lo[4], lo[5], lo[6],  lo[7]);
        o0[2] = make_float4(lo[8], lo[9], lo[10], lo[11]);
        o0[3] = make_float4(lo[12], lo[13], lo[14], lo[15]);
        o1[0] = make_float4(hi[0], hi[1], hi[2],  hi[3]);
        o1[1] = make_float4(hi[4], hi[5], hi[6],  hi[7]);
        o1[2] = make_float4(hi[8], hi[9], hi[10], hi[11]);
        o1[3] = make_float4(hi[12], hi[13], hi[14], hi[15]);
        __syncthreads();
        p ^= 1;
    }
}

// =========================================================================
extern "C" void kernel_launch(void* const* d_in, const int* in_sizes, int n_in,
                              void* d_out, int out_size)
{
    (void)in_sizes; (void)n_in; (void)out_size;
    const float* obs = (const float*)d_in[0];
    const float* inp = (const float*)d_in[1];
    const float* A   = (const float*)d_in[2];
    const float* B   = (const float*)d_in[3];
    const float* C   = (const float*)d_in[4];
    const float* Q   = (const float*)d_in[5];
    const float* R   = (const float*)d_in[6];
    const float* x0  = (const float*)d_in[7];
    float* out = (float*)d_out;

    riccati_kernel<<<1, 256>>>(A, B, C, Q, R);
    fill_kernel<<<SEQ - 1, 224>>>();
    phi_kernel<<<NCH, 256>>>();
    psi_kernel<<<NGRP, 256>>>();
    vpass_kernel<<<NCH, 128>>>(obs, inp);
    gscanA_kernel<<<NGRP * 16, 256>>>();
    gscanB_kernel<<<BATCH / 16, 256>>>(x0);
    gscanC_kernel<<<NGRP * 16, 256>>>();
    outpass_kernel<<<NCH, 128>>>(obs, inp, out);
}

// round 10
// speedup vs baseline: 1.1229x; 1.0730x over previous
#include <cuda_runtime.h>
#include <cstdint>
#include <cstddef>

#define SEQ   4096
#define BATCH 256
#define NS    16
#define MS    8
#define US    4
#define LCH   8           // chunk length
#define NCH   512         // chunks
#define GRP   16          // chunks per group
#define NGRP  32          // groups
#define GQ    448         // gain scalars per t: M(256)|N(64)|K(128)

// ---------------- device scratch ----------------
__device__ __align__(16) float2 d_G2[(size_t)SEQ * GQ];   // duplicated (g,g) pairs
__device__ int d_tlast;                                   // last distinct gain index
__device__ __align__(16) float d_Phi[NCH * 256];
__device__ __align__(16) float d_Psi[NGRP * 256];
__device__ __align__(16) float d_V  [(size_t)NCH  * BATCH * NS];
__device__ __align__(16) float d_GV [(size_t)NGRP * BATCH * NS];
__device__ __align__(16) float d_GS [(size_t)NGRP * BATCH * NS];
__device__ __align__(16) float d_Sst[(size_t)NCH  * BATCH * NS];

// ---------------- grid barrier (epoch-based, replay-safe) ----------------
__device__ unsigned int g_cnt = 0;
__device__ volatile unsigned int g_epoch = 0;

__device__ __forceinline__ void gsync(unsigned int target)
{
    __syncthreads();
    if (threadIdx.x == 0) {
        __threadfence();
        unsigned int prev = atomicAdd(&g_cnt, 1u);
        if (prev == gridDim.x - 1u) {
            atomicExch(&g_cnt, 0u);
            __threadfence();
            g_epoch = target;
        } else {
            while (g_epoch != target) __nanosleep(64);
        }
        __threadfence();
    }
    __syncthreads();
}

// ---------------- f32x2 helpers ----------------
__device__ __forceinline__ unsigned long long ffma2(unsigned long long a, unsigned long long b, unsigned long long c) {
    unsigned long long d;
    asm("fma.rn.f32x2 %0, %1, %2, %3;" : "=l"(d) : "l"(a), "l"(b), "l"(c));
    return d;
}
__device__ __forceinline__ unsigned long long fmul2(unsigned long long a, unsigned long long b) {
    unsigned long long d;
    asm("mul.rn.f32x2 %0, %1, %2;" : "=l"(d) : "l"(a), "l"(b));
    return d;
}
__device__ __forceinline__ unsigned long long pack2(float x, float y) {
    unsigned long long r;
    asm("mov.b64 %0, {%1, %2};" : "=l"(r) : "f"(x), "f"(y));
    return r;
}
__device__ __forceinline__ void unpk2(unsigned long long v, float& lo, float& hi) {
    asm("mov.b64 {%0, %1}, %2;" : "=f"(lo), "=f"(hi) : "l"(v));
}

// =========================================================================
// Kernel 1: serial Riccati recursion (one block)
// =========================================================================
__global__ void __launch_bounds__(256) riccati_kernel(
    const float* __restrict__ A, const float* __restrict__ B,
    const float* __restrict__ C, const float* __restrict__ Q,
    const float* __restrict__ R)
{
    __shared__ float sA[256], sB[64], sC[128], sQ[256], sR[64];
    __shared__ float sCA[128], sCB[32], sCQ[128], sSR0[64];
    __shared__ float sP[256], sT1[256], sPp[256], sCT[128], sW[128], sK[128], sSm[64], sSi[64];

    const int tid = threadIdx.x;
    const int i  = tid >> 4;
    const int jc = tid & 15;

    sA[tid] = A[tid];
    sQ[tid] = Q[tid];
    if (tid < 64)  { sB[tid] = B[tid]; sR[tid] = R[tid]; }
    if (tid < 128) sC[tid] = C[tid];
    sP[tid] = (i == jc) ? 1.0f : 0.0f;   // P0 = I
    __syncthreads();

    if (tid < 128) {                      // CA = C*A, CQ = C*Q  (8x16)
        float a = 0.f, q = 0.f;
        int m = tid >> 4, jj = tid & 15;
        #pragma unroll
        for (int k = 0; k < 16; ++k) {
            a += sC[m * 16 + k] * sA[k * 16 + jj];
            q += sC[m * 16 + k] * sQ[k * 16 + jj];
        }
        sCA[tid] = a; sCQ[tid] = q;
    }
    if (tid < 32) {                       // CB = C*B  (8x4)
        float a = 0.f;
        #pragma unroll
        for (int k = 0; k < 16; ++k) a += sC[(tid >> 2) * 16 + k] * sB[k * 4 + (tid & 3)];
        sCB[tid] = a;
    }
    __syncthreads();
    if (tid < 64) {                       // SR0 = CQ*C^T + R (8x8)
        int m = tid >> 3, n = tid & 7;
        float s = sR[tid];
        #pragma unroll
        for (int k = 0; k < 16; ++k) s += sCQ[m * 16 + k] * sC[n * 16 + k];
        sSR0[tid] = s;
    }
    __syncthreads();

    int tconv = SEQ;
    for (int t = 1; t < SEQ; ++t) {
        // (1) T1 = A * P
        float a = 0.f;
        #pragma unroll
        for (int k = 0; k < 16; ++k) a += sA[i * 16 + k] * sP[k * 16 + jc];
        sT1[tid] = a;
        __syncthreads();
        // (2) Ppri = T1*A^T + Q (all)  ;  CT = C*T1 (tid<128)
        a = sQ[tid];
        #pragma unroll
        for (int k = 0; k < 16; ++k) a += sT1[i * 16 + k] * sA[jc * 16 + k];
        sPp[tid] = a;
        if (tid < 128) {
            int m = tid >> 4, jj = tid & 15;
            float w = 0.f;
            #pragma unroll
            for (int k = 0; k < 16; ++k) w += sC[m * 16 + k] * sT1[k * 16 + jj];
            sCT[tid] = w;
        }
        __syncthreads();
        // (3) W = CT*A^T + CQ (tid<128)  ;  S = CT*CA^T + SR0 (tid 128..191)
        if (tid < 128) {
            int m = tid >> 4, jj = tid & 15;
            float w = sCQ[tid];
            #pragma unroll
            for (int k = 0; k < 16; ++k) w += sCT[m * 16 + k] * sA[jj * 16 + k];
            sW[tid] = w;
        } else if (tid < 192) {
            int q = tid - 128, m = q >> 3, n = q & 7;
            float s = sSR0[q];
            #pragma unroll
            for (int k = 0; k < 16; ++k) s += sCT[m * 16 + k] * sCA[n * 16 + k];
            sSm[q] = s;
        }
        __syncthreads();
        // (4) Sinv: warp-synchronous Gauss-Jordan (8 lanes, SPD)
        if (tid < 8) {
            float row[16];
            #pragma unroll
            for (int c = 0; c < 8; ++c) { row[c] = sSm[tid * 8 + c]; row[c + 8] = (c == tid) ? 1.f : 0.f; }
            #pragma unroll
            for (int p = 0; p < 8; ++p) {
                float pv  = __shfl_sync(0xFFu, row[p], p, 8);
                float f   = row[p];
                float inv = 1.0f / pv;
                #pragma unroll
                for (int c = 0; c < 16; ++c) {
                    float pr = __shfl_sync(0xFFu, row[c], p, 8) * inv;
                    row[c] = (tid == p) ? pr : (row[c] - f * pr);
                }
            }
            #pragma unroll
            for (int c = 0; c < 8; ++c) sSi[tid * 8 + c] = row[c + 8];
        }
        __syncthreads();
        // (5) K = W^T * Sinv  (16x8)
        if (tid < 128) {
            int ii = tid >> 3, m = tid & 7;
            float kk = 0.f;
            #pragma unroll
            for (int n = 0; n < 8; ++n) kk += sW[n * 16 + ii] * sSi[n * 8 + m];
            sK[tid] = kk;
        }
        __syncthreads();
        // (6) outputs + Ppost + convergence
        {
            float mm = sA[tid];                         // M = A - K*CA
            #pragma unroll
            for (int m = 0; m < 8; ++m) mm -= sK[i * 8 + m] * sCA[m * 16 + jc];
            d_G2[(size_t)t * GQ + tid] = make_float2(mm, mm);
        }
        if (tid < 64) {                                 // N = B - K*CB
            int ii = tid >> 2, u = tid & 3;
            float nn = sB[tid];
            #pragma unroll
            for (int m = 0; m < 8; ++m) nn -= sK[ii * 8 + m] * sCB[m * 4 + u];
            d_G2[(size_t)t * GQ + 256 + tid] = make_float2(nn, nn);
        }
        if (tid < 128) {
            float kk = sK[tid];
            d_G2[(size_t)t * GQ + 320 + tid] = make_float2(kk, kk);
        }
        float pn = sPp[tid];                            // Ppost = Ppri - K*W
        #pragma unroll
        for (int m = 0; m < 8; ++m) pn -= sK[i * 8 + m] * sW[m * 16 + jc];
        int pred = fabsf(pn - sP[tid]) < 1e-5f;
        sP[tid] = pn;
        int conv = __syncthreads_and(pred);
        if (conv) { tconv = t + 1; break; }
    }
    __syncthreads();
    if (tid == 0) d_tlast = (tconv < SEQ) ? (tconv - 1) : (SEQ - 1);
}

// =========================================================================
// packed affine step:  x <- M x + N u + K z   for a batch pair
// =========================================================================
__device__ __forceinline__ void kstep2(unsigned long long x[NS],
                                       const unsigned long long* __restrict__ g,
                                       const unsigned long long zz[MS],
                                       const unsigned long long uu[US])
{
    unsigned long long acc[NS];
    #pragma unroll
    for (int i = 0; i < NS; ++i) {
        const unsigned long long* gm = g + i * 16;
        const unsigned long long* gn = g + 256 + i * 4;
        const unsigned long long* gk = g + 320 + i * 8;
        unsigned long long a = fmul2(gn[0], uu[0]);
        a = ffma2(gn[1], uu[1], a);
        a = ffma2(gn[2], uu[2], a);
        a = ffma2(gn[3], uu[3], a);
        #pragma unroll
        for (int m = 0; m < MS; ++m) a = ffma2(gk[m], zz[m], a);
        #pragma unroll
        for (int k = 0; k < NS; ++k) a = ffma2(gm[k], x[k], a);
        acc[i] = a;
    }
    #pragma unroll
    for (int i = 0; i < NS; ++i) x[i] = acc[i];
}

__device__ __forceinline__ void load_zu2(const float* __restrict__ obs,
                                         const float* __restrict__ inp,
                                         int b0, int b1, int t,
                                         unsigned long long zz[MS], unsigned long long uu[US])
{
    const float4* z0p = reinterpret_cast<const float4*>(obs + ((size_t)b0 * SEQ + t) * MS);
    const float4* z1p = reinterpret_cast<const float4*>(obs + ((size_t)b1 * SEQ + t) * MS);
    float4 a0 = __ldg(z0p), a1 = __ldg(z0p + 1);
    float4 c0 = __ldg(z1p), c1 = __ldg(z1p + 1);
    zz[0] = pack2(a0.x, c0.x); zz[1] = pack2(a0.y, c0.y);
    zz[2] = pack2(a0.z, c0.z); zz[3] = pack2(a0.w, c0.w);
    zz[4] = pack2(a1.x, c1.x); zz[5] = pack2(a1.y, c1.y);
    zz[6] = pack2(a1.z, c1.z); zz[7] = pack2(a1.w, c1.w);
    float4 u0 = __ldg(reinterpret_cast<const float4*>(inp + ((size_t)b0 * SEQ + t) * US));
    float4 u1 = __ldg(reinterpret_cast<const float4*>(inp + ((size_t)b1 * SEQ + t) * US));
    uu[0] = pack2(u0.x, u1.x); uu[1] = pack2(u0.y, u1.y);
    uu[2] = pack2(u0.z, u1.z); uu[3] = pack2(u0.w, u1.w);
}

// ---------------- 16-lane shuffle matvec: a = v + P(row i) * s ----------------
// PLAIN loads: rowbase points at data written earlier in this same kernel,
// so the non-coherent __ldg path is illegal here (round-9 bug).
__device__ __forceinline__ float affine16(const float* rowbase, float v, float s)
{
    const float4* pr = reinterpret_cast<const float4*>(rowbase);
    float4 p0 = pr[0], p1 = pr[1], p2 = pr[2], p3 = pr[3];
    float a = v;
    a += p0.x * __shfl_sync(0xFFFFFFFFu, s, 0, 16)  + p0.y * __shfl_sync(0xFFFFFFFFu, s, 1, 16)
       + p0.z * __shfl_sync(0xFFFFFFFFu, s, 2, 16)  + p0.w * __shfl_sync(0xFFFFFFFFu, s, 3, 16);
    a += p1.x * __shfl_sync(0xFFFFFFFFu, s, 4, 16)  + p1.y * __shfl_sync(0xFFFFFFFFu, s, 5, 16)
       + p1.z * __shfl_sync(0xFFFFFFFFu, s, 6, 16)  + p1.w * __shfl_sync(0xFFFFFFFFu, s, 7, 16);
    a += p2.x * __shfl_sync(0xFFFFFFFFu, s, 8, 16)  + p2.y * __shfl_sync(0xFFFFFFFFu, s, 9, 16)
       + p2.z * __shfl_sync(0xFFFFFFFFu, s, 10, 16) + p2.w * __shfl_sync(0xFFFFFFFFu, s, 11, 16);
    a += p3.x * __shfl_sync(0xFFFFFFFFu, s, 12, 16) + p3.y * __shfl_sync(0xFFFFFFFFu, s, 13, 16)
       + p3.z * __shfl_sync(0xFFFFFFFFu, s, 14, 16) + p3.w * __shfl_sync(0xFFFFFFFFu, s, 15, 16);
    return a;
}

// =========================================================================
// Kernel 2: fused persistent kernel — phi+vpass | psi+gscanA | gscanB |
//           gscanC | outpass, separated by grid barriers.
// =========================================================================
__global__ void __launch_bounds__(128, 4) fused_kernel(
    const float* __restrict__ obs, const float* __restrict__ inp,
    const float* __restrict__ x0, float* __restrict__ out)
{
    __shared__ __align__(16) unsigned long long sG[LCH][GQ];  // 28672 B
    __shared__ float sPh[2][256];

    const int j   = blockIdx.x;
    const int tid = threadIdx.x;
    const int b0  = tid, b1 = tid + 128;
    const int t0  = j * LCH + 1;
    const int steps = (t0 + LCH <= SEQ) ? LCH : (SEQ - t0);

    const unsigned int E0 = g_epoch;     // per-thread; safe: epoch can't advance
    const int tlast = d_tlast;           // until all blocks reach first gsync

    // ---------------- P1a: stage all LCH gain sets (clamped index) ----------
    #pragma unroll
    for (int s = 0; s < LCH; ++s) {
        int tt = t0 + s; if (tt > tlast) tt = tlast;
        const float4* src = reinterpret_cast<const float4*>(&d_G2[(size_t)tt * GQ]);
        reinterpret_cast<float4*>(sG[s])[tid] = __ldg(src + tid);      // d_G2: written by prior launch — __ldg legal
        if (tid < 96) reinterpret_cast<float4*>(sG[s])[128 + tid] = __ldg(src + 128 + tid);
    }
    __syncthreads();

    // ---------------- P1b: Phi_j = M_{s=steps-1} * ... * M_{s=0} ------------
    {
        const float* M0 = reinterpret_cast<const float*>(sG[0]);
        sPh[0][tid]       = M0[2 * tid];
        sPh[0][tid + 128] = M0[2 * (tid + 128)];
        __syncthreads();
        int pp = 0;
        for (int s = 1; s < steps; ++s) {
            const float* Ms = reinterpret_cast<const float*>(sG[s]);
            #pragma unroll
            for (int h = 0; h < 2; ++h) {
                int e = tid + h * 128, ii = e >> 4, jc = e & 15;
                float a = 0.f;
                #pragma unroll
                for (int k = 0; k < 16; ++k) a += Ms[2 * (ii * 16 + k)] * sPh[pp][k * 16 + jc];
                sPh[pp ^ 1][e] = a;
            }
            __syncthreads();
            pp ^= 1;
        }
        d_Phi[j * 256 + tid]       = sPh[pp][tid];
        d_Phi[j * 256 + tid + 128] = sPh[pp][tid + 128];
    }

    // ---------------- P1c: vpass (zero-start chunk response) ----------------
    {
        unsigned long long x[NS];
        #pragma unroll
        for (int q = 0; q < NS; ++q) x[q] = 0ull;
        for (int s = 0; s < steps; ++s) {
            unsigned long long zz[MS], uu[US];
            load_zu2(obs, inp, b0, b1, t0 + s, zz, uu);
            kstep2(x, sG[s], zz, uu);
        }
        float lo[NS], hi[NS];
        #pragma unroll
        for (int q = 0; q < NS; ++q) unpk2(x[q], lo[q], hi[q]);
        float4* v0 = reinterpret_cast<float4*>(&d_V[((size_t)j * BATCH + b0) * NS]);
        float4* v1 = reinterpret_cast<float4*>(&d_V[((size_t)j * BATCH + b1) * NS]);
        v0[0] = make_float4(lo[0], lo[1], lo[2],  lo[3]);
        v0[1] = make_float4(lo[4], lo[5], lo[6],  lo[7]);
        v0[2] = make_float4(lo[8], lo[9], lo[10], lo[11]);
        v0[3] = make_float4(lo[12], lo[13], lo[14], lo[15]);
        v1[0] = make_float4(hi[0], hi[1], hi[2],  hi[3]);
        v1[1] = make_float4(hi[4], hi[5], hi[6],  hi[7]);
        v1[2] = make_float4(hi[8], hi[9], hi[10], hi[11]);
        v1[3] = make_float4(hi[12], hi[13], hi[14], hi[15]);
    }

    gsync(E0 + 1);

    // ---------------- P2: psi (blocks 480..511) + gscanA (all, 2 tasks) -----
    if (j >= NCH - NGRP) {
        const int g = j - (NCH - NGRP);
        sPh[0][tid]       = d_Phi[(g * GRP) * 256 + tid];
        sPh[0][tid + 128] = d_Phi[(g * GRP) * 256 + tid + 128];
        __syncthreads();
        int pp = 0;
        for (int c = 1; c < GRP; ++c) {
            const float* Ms = &d_Phi[(g * GRP + c) * 256];
            #pragma unroll
            for (int h = 0; h < 2; ++h) {
                int e = tid + h * 128, ii = e >> 4, jc = e & 15;
                float a = 0.f;
                #pragma unroll
                for (int k = 0; k < 16; ++k) a += Ms[ii * 16 + k] * sPh[pp][k * 16 + jc];
                sPh[pp ^ 1][e] = a;
            }
            __syncthreads();
            pp ^= 1;
        }
        d_Psi[g * 256 + tid]       = sPh[pp][tid];
        d_Psi[g * 256 + tid + 128] = sPh[pp][tid + 128];
    }
    {
        const int i = tid & 15;
        #pragma unroll
        for (int rep = 0; rep < 2; ++rep) {
            const int T = j + rep * NCH;          // 1024 tasks
            const int g = T >> 5, sub = T & 31;
            const int b = sub * 8 + (tid >> 4);
            float s = 0.f;
            #pragma unroll
            for (int c = 0; c < GRP; ++c) {
                const int ch = g * GRP + c;
                float v = d_V[((size_t)ch * BATCH + b) * NS + i];
                s = affine16(&d_Phi[ch * 256 + i * 16], v, s);
            }
            d_GV[((size_t)g * BATCH + b) * NS + i] = s;
        }
    }

    gsync(E0 + 2);

    // ---------------- P3: gscanB (blocks 0..31, serial over 32 groups) ------
    if (j < 32) {
        const int b = j * 8 + (tid >> 4);
        const int i = tid & 15;
        float s = __ldg(x0 + i);
        for (int g = 0; g < NGRP; ++g) {
            d_GS[((size_t)g * BATCH + b) * NS + i] = s;
            float v = d_GV[((size_t)g * BATCH + b) * NS + i];
            s = affine16(&d_Psi[g * 256 + i * 16], v, s);
        }
    }

    gsync(E0 + 3);

    // ---------------- P4a: gscanC (all blocks, 2 tasks) ---------------------
    {
        const int i = tid & 15;
        #pragma unroll
        for (int rep = 0; rep < 2; ++rep) {
            const int T = j + rep * NCH;
            const int g = T >> 5, sub = T & 31;
            const int b = sub * 8 + (tid >> 4);
            float s = d_GS[((size_t)g * BATCH + b) * NS + i];
            #pragma unroll
            for (int c = 0; c < GRP; ++c) {
                const int ch = g * GRP + c;
                d_Sst[((size_t)ch * BATCH + b) * NS + i] = s;
                float v = d_V[((size_t)ch * BATCH + b) * NS + i];
                s = affine16(&d_Phi[ch * 256 + i * 16], v, s);
            }
        }
    }

    gsync(E0 + 4);

    // ---------------- P4b: outpass (gains still resident in smem) -----------
    {
        unsigned long long x[NS];
        {
            const float4* s0 = reinterpret_cast<const float4*>(&d_Sst[((size_t)j * BATCH + b0) * NS]);
            const float4* s1 = reinterpret_cast<const float4*>(&d_Sst[((size_t)j * BATCH + b1) * NS]);
            float4 q0 = s0[0], q1 = s0[1], q2 = s0[2], q3 = s0[3];
            float4 r0 = s1[0], r1 = s1[1], r2 = s1[2], r3 = s1[3];
            x[0]  = pack2(q0.x, r0.x); x[1]  = pack2(q0.y, r0.y); x[2]  = pack2(q0.z, r0.z); x[3]  = pack2(q0.w, r0.w);
            x[4]  = pack2(q1.x, r1.x); x[5]  = pack2(q1.y, r1.y); x[6]  = pack2(q1.z, r1.z); x[7]  = pack2(q1.w, r1.w);
            x[8]  = pack2(q2.x, r2.x); x[9]  = pack2(q2.y, r2.y); x[10] = pack2(q2.z, r2.z); x[11] = pack2(q2.w, r2.w);
            x[12] = pack2(q3.x, r3.x); x[13] = pack2(q3.y, r3.y); x[14] = pack2(q3.z, r3.z); x[15] = pack2(q3.w, r3.w);
        }
        if (j == 0) {      // out[b][0] = x0 = chunk-0 start state
            float lo[NS], hi[NS];
            #pragma unroll
            for (int q = 0; q < NS; ++q) unpk2(x[q], lo[q], hi[q]);
            float4* o0 = reinterpret_cast<float4*>(out + (size_t)b0 * SEQ * NS);
            float4* o1 = reinterpret_cast<float4*>(out + (size_t)b1 * SEQ * NS);
            o0[0] = make_float4(lo[0], lo[1], lo[2],  lo[3]);
            o0[1] = make_float4(lo[4], lo[5], lo[6],  lo[7]);
            o0[2] = make_float4(lo[8], lo[9], lo[10], lo[11]);
            o0[3] = make_float4(lo[12], lo[13], lo[14], lo[15]);
            o1[0] = make_float4(hi[0], hi[1], hi[2],  hi[3]);
            o1[1] = make_float4(hi[4], hi[5], hi[6],  hi[7]);
            o1[2] = make_float4(hi[8], hi[9], hi[10], hi[11]);
            o1[3] = make_float4(hi[12], hi[13], hi[14], hi[15]);
        }
        for (int s = 0; s < steps; ++s) {
            const int t = t0 + s;
            unsigned long long zz[MS], uu[US];
            load_zu2(obs, inp, b0, b1, t, zz, uu);
            kstep2(x, sG[s], zz, uu);
            float lo[NS], hi[NS];
            #pragma unroll
            for (int q = 0; q < NS; ++q) unpk2(x[q], lo[q], hi[q]);
            float4* o0 = reinterpret_cast<float4*>(out + ((size_t)b0 * SEQ + t) * NS);
            float4* o1 = reinterpret_cast<float4*>(out + ((size_t)b1 * SEQ + t) * NS);
            o0[0] = make_float4(lo[0], lo[1], lo[2],  lo[3]);
            o0[1] = make_float4(lo[4], lo[5], lo[6],  lo[7]);
            o0[2] = make_float4(lo[8], lo[9], lo[10], lo[11]);
            o0[3] = make_float4(lo[12], lo[13], lo[14], lo[15]);
            o1[0] = make_float4(hi[0], hi[1], hi[2],  hi[3]);
            o1[1] = make_float4(hi[4], hi[5], hi[6],  hi[7]);
            o1[2] = make_float4(hi[8], hi[9], hi[10], hi[11]);
            o1[3] = make_float4(hi[12], hi[13], hi[14], hi[15]);
        }
    }
}

// =========================================================================
extern "C" void kernel_launch(void* const* d_in, const int* in_sizes, int n_in,
                              void* d_out, int out_size)
{
    (void)in_sizes; (void)n_in; (void)out_size;
    const float* obs = (const float*)d_in[0];
    const float* inp = (const float*)d_in[1];
    const float* A   = (const float*)d_in[2];
    const float* B   = (const float*)d_in[3];
    const float* C   = (const float*)d_in[4];
    const float* Q   = (const float*)d_in[5];
    const float* R   = (const float*)d_in[6];
    const float* x0  = (const float*)d_in[7];
    float* out = (float*)d_out;

    riccati_kernel<<<1, 256>>>(A, B, C, Q, R);
    fused_kernel<<<NCH, 128>>>(obs, inp, x0, out);
}

// round 11
// speedup vs baseline: 1.2031x; 1.0714x over previous
#include <cuda_runtime.h>
#include <cstdint>
#include <cstddef>

#define SEQ   4096
#define BATCH 256
#define NS    16
#define MS    8
#define US    4
#define LCH   8           // chunk length
#define NCH   512         // chunks
#define GRP   16          // chunks per group
#define NGRP  32          // groups
#define GQ    448         // gain scalars per t: M(256)|N(64)|K(128)

typedef unsigned long long u64;

// ---------------- device scratch ----------------
__device__ __align__(16) float2 d_G2[(size_t)SEQ * GQ];   // duplicated (g,g) pairs
__device__ int d_tlast;                                   // last distinct gain index
__device__ __align__(16) float d_Phi[NCH * 256];
__device__ __align__(16) float d_Psi[NGRP * 256];
__device__ __align__(16) float d_V  [(size_t)NCH  * BATCH * NS];
__device__ __align__(16) float d_GV [(size_t)NGRP * BATCH * NS];
__device__ __align__(16) float d_GS [(size_t)NGRP * BATCH * NS];
__device__ __align__(16) float d_Sst[(size_t)NCH  * BATCH * NS];
// packed drive terms c = N u + K z : [chunk*LCH+step][q(16)][tid(128)] u64
__device__ __align__(16) u64 d_C[(size_t)NCH * LCH * NS * 128];

// ---------------- grid barrier (epoch-based, replay-safe) ----------------
__device__ unsigned int g_cnt = 0;
__device__ volatile unsigned int g_epoch = 0;

__device__ __forceinline__ void gsync(unsigned int target)
{
    __syncthreads();
    if (threadIdx.x == 0) {
        __threadfence();
        unsigned int prev = atomicAdd(&g_cnt, 1u);
        if (prev == gridDim.x - 1u) {
            atomicExch(&g_cnt, 0u);
            __threadfence();
            g_epoch = target;
        } else {
            while (g_epoch != target) __nanosleep(64);
        }
        __threadfence();
    }
    __syncthreads();
}

// ---------------- f32x2 helpers ----------------
__device__ __forceinline__ u64 ffma2(u64 a, u64 b, u64 c) {
    u64 d;
    asm("fma.rn.f32x2 %0, %1, %2, %3;" : "=l"(d) : "l"(a), "l"(b), "l"(c));
    return d;
}
__device__ __forceinline__ u64 fmul2(u64 a, u64 b) {
    u64 d;
    asm("mul.rn.f32x2 %0, %1, %2;" : "=l"(d) : "l"(a), "l"(b));
    return d;
}
__device__ __forceinline__ u64 pack2(float x, float y) {
    u64 r;
    asm("mov.b64 %0, {%1, %2};" : "=l"(r) : "f"(x), "f"(y));
    return r;
}
__device__ __forceinline__ void unpk2(u64 v, float& lo, float& hi) {
    asm("mov.b64 {%0, %1}, %2;" : "=f"(lo), "=f"(hi) : "l"(v));
}

// =========================================================================
// Kernel 1: serial Riccati recursion (one block)
// =========================================================================
__global__ void __launch_bounds__(256) riccati_kernel(
    const float* __restrict__ A, const float* __restrict__ B,
    const float* __restrict__ C, const float* __restrict__ Q,
    const float* __restrict__ R)
{
    __shared__ float sA[256], sB[64], sC[128], sQ[256], sR[64];
    __shared__ float sCA[128], sCB[32], sCQ[128], sSR0[64];
    __shared__ float sP[256], sT1[256], sPp[256], sCT[128], sW[128], sK[128], sSm[64], sSi[64];

    const int tid = threadIdx.x;
    const int i  = tid >> 4;
    const int jc = tid & 15;

    sA[tid] = A[tid];
    sQ[tid] = Q[tid];
    if (tid < 64)  { sB[tid] = B[tid]; sR[tid] = R[tid]; }
    if (tid < 128) sC[tid] = C[tid];
    sP[tid] = (i == jc) ? 1.0f : 0.0f;   // P0 = I
    __syncthreads();

    if (tid < 128) {                      // CA = C*A, CQ = C*Q  (8x16)
        float a = 0.f, q = 0.f;
        int m = tid >> 4, jj = tid & 15;
        #pragma unroll
        for (int k = 0; k < 16; ++k) {
            a += sC[m * 16 + k] * sA[k * 16 + jj];
            q += sC[m * 16 + k] * sQ[k * 16 + jj];
        }
        sCA[tid] = a; sCQ[tid] = q;
    }
    if (tid < 32) {                       // CB = C*B  (8x4)
        float a = 0.f;
        #pragma unroll
        for (int k = 0; k < 16; ++k) a += sC[(tid >> 2) * 16 + k] * sB[k * 4 + (tid & 3)];
        sCB[tid] = a;
    }
    __syncthreads();
    if (tid < 64) {                       // SR0 = CQ*C^T + R (8x8)
        int m = tid >> 3, n = tid & 7;
        float s = sR[tid];
        #pragma unroll
        for (int k = 0; k < 16; ++k) s += sCQ[m * 16 + k] * sC[n * 16 + k];
        sSR0[tid] = s;
    }
    __syncthreads();

    int tconv = SEQ;
    for (int t = 1; t < SEQ; ++t) {
        // (1) T1 = A * P
        float a = 0.f;
        #pragma unroll
        for (int k = 0; k < 16; ++k) a += sA[i * 16 + k] * sP[k * 16 + jc];
        sT1[tid] = a;
        __syncthreads();
        // (2) Ppri = T1*A^T + Q (all)  ;  CT = C*T1 (tid<128)
        a = sQ[tid];
        #pragma unroll
        for (int k = 0; k < 16; ++k) a += sT1[i * 16 + k] * sA[jc * 16 + k];
        sPp[tid] = a;
        if (tid < 128) {
            int m = tid >> 4, jj = tid & 15;
            float w = 0.f;
            #pragma unroll
            for (int k = 0; k < 16; ++k) w += sC[m * 16 + k] * sT1[k * 16 + jj];
            sCT[tid] = w;
        }
        __syncthreads();
        // (3) W = CT*A^T + CQ (tid<128)  ;  S = CT*CA^T + SR0 (tid 128..191)
        if (tid < 128) {
            int m = tid >> 4, jj = tid & 15;
            float w = sCQ[tid];
            #pragma unroll
            for (int k = 0; k < 16; ++k) w += sCT[m * 16 + k] * sA[jj * 16 + k];
            sW[tid] = w;
        } else if (tid < 192) {
            int q = tid - 128, m = q >> 3, n = q & 7;
            float s = sSR0[q];
            #pragma unroll
            for (int k = 0; k < 16; ++k) s += sCT[m * 16 + k] * sCA[n * 16 + k];
            sSm[q] = s;
        }
        __syncthreads();
        // (4) Sinv: warp-synchronous Gauss-Jordan (8 lanes, SPD)
        if (tid < 8) {
            float row[16];
            #pragma unroll
            for (int c = 0; c < 8; ++c) { row[c] = sSm[tid * 8 + c]; row[c + 8] = (c == tid) ? 1.f : 0.f; }
            #pragma unroll
            for (int p = 0; p < 8; ++p) {
                float pv  = __shfl_sync(0xFFu, row[p], p, 8);
                float f   = row[p];
                float inv = 1.0f / pv;
                #pragma unroll
                for (int c = 0; c < 16; ++c) {
                    float pr = __shfl_sync(0xFFu, row[c], p, 8) * inv;
                    row[c] = (tid == p) ? pr : (row[c] - f * pr);
                }
            }
            #pragma unroll
            for (int c = 0; c < 8; ++c) sSi[tid * 8 + c] = row[c + 8];
        }
        __syncthreads();
        // (5) K = W^T * Sinv  (16x8)
        if (tid < 128) {
            int ii = tid >> 3, m = tid & 7;
            float kk = 0.f;
            #pragma unroll
            for (int n = 0; n < 8; ++n) kk += sW[n * 16 + ii] * sSi[n * 8 + m];
            sK[tid] = kk;
        }
        __syncthreads();
        // (6) outputs + Ppost + convergence
        {
            float mm = sA[tid];                         // M = A - K*CA
            #pragma unroll
            for (int m = 0; m < 8; ++m) mm -= sK[i * 8 + m] * sCA[m * 16 + jc];
            d_G2[(size_t)t * GQ + tid] = make_float2(mm, mm);
        }
        if (tid < 64) {                                 // N = B - K*CB
            int ii = tid >> 2, u = tid & 3;
            float nn = sB[tid];
            #pragma unroll
            for (int m = 0; m < 8; ++m) nn -= sK[ii * 8 + m] * sCB[m * 4 + u];
            d_G2[(size_t)t * GQ + 256 + tid] = make_float2(nn, nn);
        }
        if (tid < 128) {
            float kk = sK[tid];
            d_G2[(size_t)t * GQ + 320 + tid] = make_float2(kk, kk);
        }
        float pn = sPp[tid];                            // Ppost = Ppri - K*W
        #pragma unroll
        for (int m = 0; m < 8; ++m) pn -= sK[i * 8 + m] * sW[m * 16 + jc];
        int pred = fabsf(pn - sP[tid]) < 1e-5f;
        sP[tid] = pn;
        int conv = __syncthreads_and(pred);
        if (conv) { tconv = t + 1; break; }
    }
    __syncthreads();
    if (tid == 0) d_tlast = (tconv < SEQ) ? (tconv - 1) : (SEQ - 1);
}

// =========================================================================
// drive term:  c_i = N_i·u + K_i·z  (same FMA order as original kstep2)
// =========================================================================
__device__ __forceinline__ void compute_c(u64 c[NS], const u64* __restrict__ g,
                                          const u64 zz[MS], const u64 uu[US])
{
    #pragma unroll
    for (int i = 0; i < NS; ++i) {
        const ulonglong2* gn = reinterpret_cast<const ulonglong2*>(g + 256 + i * 4);
        const ulonglong2* gk = reinterpret_cast<const ulonglong2*>(g + 320 + i * 8);
        ulonglong2 n0 = gn[0], n1 = gn[1];
        u64 a = fmul2(n0.x, uu[0]);
        a = ffma2(n0.y, uu[1], a);
        a = ffma2(n1.x, uu[2], a);
        a = ffma2(n1.y, uu[3], a);
        ulonglong2 k0 = gk[0], k1 = gk[1], k2 = gk[2], k3 = gk[3];
        a = ffma2(k0.x, zz[0], a); a = ffma2(k0.y, zz[1], a);
        a = ffma2(k1.x, zz[2], a); a = ffma2(k1.y, zz[3], a);
        a = ffma2(k2.x, zz[4], a); a = ffma2(k2.y, zz[5], a);
        a = ffma2(k3.x, zz[6], a); a = ffma2(k3.y, zz[7], a);
        c[i] = a;
    }
}

// recursion step:  x <- M x + c   (128-bit shared loads)
__device__ __forceinline__ void kstepm(u64 x[NS], const u64* __restrict__ g,
                                       const u64 c[NS])
{
    u64 acc[NS];
    #pragma unroll
    for (int i = 0; i < NS; ++i) {
        const ulonglong2* gm = reinterpret_cast<const ulonglong2*>(g + i * 16);
        u64 a = c[i];
        #pragma unroll
        for (int k = 0; k < 8; ++k) {
            ulonglong2 m2 = gm[k];
            a = ffma2(m2.x, x[2 * k],     a);
            a = ffma2(m2.y, x[2 * k + 1], a);
        }
        acc[i] = a;
    }
    #pragma unroll
    for (int i = 0; i < NS; ++i) x[i] = acc[i];
}

__device__ __forceinline__ void load_zu2(const float* __restrict__ obs,
                                         const float* __restrict__ inp,
                                         int b0, int b1, int t,
                                         u64 zz[MS], u64 uu[US])
{
    const float4* z0p = reinterpret_cast<const float4*>(obs + ((size_t)b0 * SEQ + t) * MS);
    const float4* z1p = reinterpret_cast<const float4*>(obs + ((size_t)b1 * SEQ + t) * MS);
    float4 a0 = __ldg(z0p), a1 = __ldg(z0p + 1);
    float4 c0 = __ldg(z1p), c1 = __ldg(z1p + 1);
    zz[0] = pack2(a0.x, c0.x); zz[1] = pack2(a0.y, c0.y);
    zz[2] = pack2(a0.z, c0.z); zz[3] = pack2(a0.w, c0.w);
    zz[4] = pack2(a1.x, c1.x); zz[5] = pack2(a1.y, c1.y);
    zz[6] = pack2(a1.z, c1.z); zz[7] = pack2(a1.w, c1.w);
    float4 u0 = __ldg(reinterpret_cast<const float4*>(inp + ((size_t)b0 * SEQ + t) * US));
    float4 u1 = __ldg(reinterpret_cast<const float4*>(inp + ((size_t)b1 * SEQ + t) * US));
    uu[0] = pack2(u0.x, u1.x); uu[1] = pack2(u0.y, u1.y);
    uu[2] = pack2(u0.z, u1.z); uu[3] = pack2(u0.w, u1.w);
}

// ---------------- 16-lane shuffle matvec: a = v + P(row i) * s ----------------
// PLAIN loads: data written earlier in this same kernel.
__device__ __forceinline__ float affine16(const float* rowbase, float v, float s)
{
    const float4* pr = reinterpret_cast<const float4*>(rowbase);
    float4 p0 = pr[0], p1 = pr[1], p2 = pr[2], p3 = pr[3];
    float a = v;
    a += p0.x * __shfl_sync(0xFFFFFFFFu, s, 0, 16)  + p0.y * __shfl_sync(0xFFFFFFFFu, s, 1, 16)
       + p0.z * __shfl_sync(0xFFFFFFFFu, s, 2, 16)  + p0.w * __shfl_sync(0xFFFFFFFFu, s, 3, 16);
    a += p1.x * __shfl_sync(0xFFFFFFFFu, s, 4, 16)  + p1.y * __shfl_sync(0xFFFFFFFFu, s, 5, 16)
       + p1.z * __shfl_sync(0xFFFFFFFFu, s, 6, 16)  + p1.w * __shfl_sync(0xFFFFFFFFu, s, 7, 16);
    a += p2.x * __shfl_sync(0xFFFFFFFFu, s, 8, 16)  + p2.y * __shfl_sync(0xFFFFFFFFu, s, 9, 16)
       + p2.z * __shfl_sync(0xFFFFFFFFu, s, 10, 16) + p2.w * __shfl_sync(0xFFFFFFFFu, s, 11, 16);
    a += p3.x * __shfl_sync(0xFFFFFFFFu, s, 12, 16) + p3.y * __shfl_sync(0xFFFFFFFFu, s, 13, 16)
       + p3.z * __shfl_sync(0xFFFFFFFFu, s, 14, 16) + p3.w * __shfl_sync(0xFFFFFFFFu, s, 15, 16);
    return a;
}

// =========================================================================
// Kernel 2: fused persistent kernel — (c+phi+vpass) | psi+gscanA | gscanB |
//           gscanC | outpass, separated by grid barriers.
// =========================================================================
__global__ void __launch_bounds__(128, 4) fused_kernel(
    const float* __restrict__ obs, const float* __restrict__ inp,
    const float* __restrict__ x0, float* __restrict__ out)
{
    __shared__ __align__(16) u64 sG[LCH][GQ];  // 28672 B
    __shared__ float sPh[2][256];

    const int j   = blockIdx.x;
    const int tid = threadIdx.x;
    const int b0  = tid, b1 = tid + 128;
    const int t0  = j * LCH + 1;
    const int steps = (t0 + LCH <= SEQ) ? LCH : (SEQ - t0);

    const unsigned int E0 = g_epoch;     // per-thread; safe: epoch can't advance
    const int tlast = d_tlast;           // until all blocks reach first gsync

    // ---------------- P1a: stage all LCH gain sets (clamped index) ----------
    #pragma unroll
    for (int s = 0; s < LCH; ++s) {
        int tt = t0 + s; if (tt > tlast) tt = tlast;
        const float4* src = reinterpret_cast<const float4*>(&d_G2[(size_t)tt * GQ]);
        reinterpret_cast<float4*>(sG[s])[tid] = __ldg(src + tid);      // d_G2: prior launch — __ldg legal
        if (tid < 96) reinterpret_cast<float4*>(sG[s])[128 + tid] = __ldg(src + 128 + tid);
    }
    __syncthreads();

    // ---------------- P1b: Phi_j = M_{s=steps-1} * ... * M_{s=0} ------------
    {
        const float* M0 = reinterpret_cast<const float*>(sG[0]);
        sPh[0][tid]       = M0[2 * tid];
        sPh[0][tid + 128] = M0[2 * (tid + 128)];
        __syncthreads();
        int pp = 0;
        for (int s = 1; s < steps; ++s) {
            const float* Ms = reinterpret_cast<const float*>(sG[s]);
            #pragma unroll
            for (int h = 0; h < 2; ++h) {
                int e = tid + h * 128, ii = e >> 4, jc = e & 15;
                float a = 0.f;
                #pragma unroll
                for (int k = 0; k < 16; ++k) a += Ms[2 * (ii * 16 + k)] * sPh[pp][k * 16 + jc];
                sPh[pp ^ 1][e] = a;
            }
            __syncthreads();
            pp ^= 1;
        }
        d_Phi[j * 256 + tid]       = sPh[pp][tid];
        d_Phi[j * 256 + tid + 128] = sPh[pp][tid + 128];
    }

    // ---------------- P1c: vpass + drive-term precompute ---------------------
    {
        u64 x[NS];
        #pragma unroll
        for (int q = 0; q < NS; ++q) x[q] = 0ull;
        for (int s = 0; s < steps; ++s) {
            u64 zz[MS], uu[US], c[NS];
            load_zu2(obs, inp, b0, b1, t0 + s, zz, uu);
            compute_c(c, sG[s], zz, uu);
            // store c coalesced: lane-major layout [ (j*LCH+s)*16 + q ][ tid ]
            {
                u64* cb = &d_C[((size_t)(j * LCH + s) * NS) * 128 + tid];
                #pragma unroll
                for (int q = 0; q < NS; ++q) cb[q * 128] = c[q];
            }
            kstepm(x, sG[s], c);
        }
        float lo[NS], hi[NS];
        #pragma unroll
        for (int q = 0; q < NS; ++q) unpk2(x[q], lo[q], hi[q]);
        float4* v0 = reinterpret_cast<float4*>(&d_V[((size_t)j * BATCH + b0) * NS]);
        float4* v1 = reinterpret_cast<float4*>(&d_V[((size_t)j * BATCH + b1) * NS]);
        v0[0] = make_float4(lo[0], lo[1], lo[2],  lo[3]);
        v0[1] = make_float4(lo[4], lo[5], lo[6],  lo[7]);
        v0[2] = make_float4(lo[8], lo[9], lo[10], lo[11]);
        v0[3] = make_float4(lo[12], lo[13], lo[14], lo[15]);
        v1[0] = make_float4(hi[0], hi[1], hi[2],  hi[3]);
        v1[1] = make_float4(hi[4], hi[5], hi[6],  hi[7]);
        v1[2] = make_float4(hi[8], hi[9], hi[10], hi[11]);
        v1[3] = make_float4(hi[12], hi[13], hi[14], hi[15]);
    }

    gsync(E0 + 1);

    // ---------------- P2: psi (blocks 480..511) + gscanA (all, 2 tasks) -----
    if (j >= NCH - NGRP) {
        const int g = j - (NCH - NGRP);
        sPh[0][tid]       = d_Phi[(g * GRP) * 256 + tid];
        sPh[0][tid + 128] = d_Phi[(g * GRP) * 256 + tid + 128];
        __syncthreads();
        int pp = 0;
        for (int c = 1; c < GRP; ++c) {
            const float* Ms = &d_Phi[(g * GRP + c) * 256];
            #pragma unroll
            for (int h = 0; h < 2; ++h) {
                int e = tid + h * 128, ii = e >> 4, jc = e & 15;
                float a = 0.f;
                #pragma unroll
                for (int k = 0; k < 16; ++k) a += Ms[ii * 16 + k] * sPh[pp][k * 16 + jc];
                sPh[pp ^ 1][e] = a;
            }
            __syncthreads();
            pp ^= 1;
        }
        d_Psi[g * 256 + tid]       = sPh[pp][tid];
        d_Psi[g * 256 + tid + 128] = sPh[pp][tid + 128];
    }
    {
        const int i = tid & 15;
        #pragma unroll
        for (int rep = 0; rep < 2; ++rep) {
            const int T = j + rep * NCH;          // 1024 tasks
            const int g = T >> 5, sub = T & 31;
            const int b = sub * 8 + (tid >> 4);
            float s = 0.f;
            #pragma unroll
            for (int c = 0; c < GRP; ++c) {
                const int ch = g * GRP + c;
                float v = d_V[((size_t)ch * BATCH + b) * NS + i];
                s = affine16(&d_Phi[ch * 256 + i * 16], v, s);
            }
            d_GV[((size_t)g * BATCH + b) * NS + i] = s;
        }
    }

    gsync(E0 + 2);

    // ---------------- P3: gscanB (blocks 0..31, serial over 32 groups) ------
    if (j < 32) {
        const int b = j * 8 + (tid >> 4);
        const int i = tid & 15;
        float s = __ldg(x0 + i);
        for (int g = 0; g < NGRP; ++g) {
            d_GS[((size_t)g * BATCH + b) * NS + i] = s;
            float v = d_GV[((size_t)g * BATCH + b) * NS + i];
            s = affine16(&d_Psi[g * 256 + i * 16], v, s);
        }
    }

    gsync(E0 + 3);

    // ---------------- P4a: gscanC (all blocks, 2 tasks) ---------------------
    {
        const int i = tid & 15;
        #pragma unroll
        for (int rep = 0; rep < 2; ++rep) {
            const int T = j + rep * NCH;
            const int g = T >> 5, sub = T & 31;
            const int b = sub * 8 + (tid >> 4);
            float s = d_GS[((size_t)g * BATCH + b) * NS + i];
            #pragma unroll
            for (int c = 0; c < GRP; ++c) {
                const int ch = g * GRP + c;
                d_Sst[((size_t)ch * BATCH + b) * NS + i] = s;
                float v = d_V[((size_t)ch * BATCH + b) * NS + i];
                s = affine16(&d_Phi[ch * 256 + i * 16], v, s);
            }
        }
    }

    gsync(E0 + 4);

    // ---------------- P4b: outpass — x = M x + c only (gains in smem) -------
    {
        u64 x[NS];
        {
            const float4* s0 = reinterpret_cast<const float4*>(&d_Sst[((size_t)j * BATCH + b0) * NS]);
            const float4* s1 = reinterpret_cast<const float4*>(&d_Sst[((size_t)j * BATCH + b1) * NS]);
            float4 q0 = s0[0], q1 = s0[1], q2 = s0[2], q3 = s0[3];
            float4 r0 = s1[0], r1 = s1[1], r2 = s1[2], r3 = s1[3];
            x[0]  = pack2(q0.x, r0.x); x[1]  = pack2(q0.y, r0.y); x[2]  = pack2(q0.z, r0.z); x[3]  = pack2(q0.w, r0.w);
            x[4]  = pack2(q1.x, r1.x); x[5]  = pack2(q1.y, r1.y); x[6]  = pack2(q1.z, r1.z); x[7]  = pack2(q1.w, r1.w);
            x[8]  = pack2(q2.x, r2.x); x[9]  = pack2(q2.y, r2.y); x[10] = pack2(q2.z, r2.z); x[11] = pack2(q2.w, r2.w);
            x[12] = pack2(q3.x, r3.x); x[13] = pack2(q3.y, r3.y); x[14] = pack2(q3.z, r3.z); x[15] = pack2(q3.w, r3.w);
        }
        if (j == 0) {      // out[b][0] = x0 = chunk-0 start state
            float lo[NS], hi[NS];
            #pragma unroll
            for (int q = 0; q < NS; ++q) unpk2(x[q], lo[q], hi[q]);
            float4* o0 = reinterpret_cast<float4*>(out + (size_t)b0 * SEQ * NS);
            float4* o1 = reinterpret_cast<float4*>(out + (size_t)b1 * SEQ * NS);
            o0[0] = make_float4(lo[0], lo[1], lo[2],  lo[3]);
            o0[1] = make_float4(lo[4], lo[5], lo[6],  lo[7]);
            o0[2] = make_float4(lo[8], lo[9], lo[10], lo[11]);
            o0[3] = make_float4(lo[12], lo[13], lo[14], lo[15]);
            o1[0] = make_float4(hi[0], hi[1], hi[2],  hi[3]);
            o1[1] = make_float4(hi[4], hi[5], hi[6],  hi[7]);
            o1[2] = make_float4(hi[8], hi[9], hi[10], hi[11]);
            o1[3] = make_float4(hi[12], hi[13], hi[14], hi[15]);
        }
        for (int s = 0; s < steps; ++s) {
            const int t = t0 + s;
            u64 c[NS];
            {   // reload drive terms (same thread wrote them — coalesced, L2-hot)
                const u64* cb = &d_C[((size_t)(j * LCH + s) * NS) * 128 + tid];
                #pragma unroll
                for (int q = 0; q < NS; ++q) c[q] = cb[q * 128];
            }
            kstepm(x, sG[s], c);
            float lo[NS], hi[NS];
            #pragma unroll
            for (int q = 0; q < NS; ++q) unpk2(x[q], lo[q], hi[q]);
            float4* o0 = reinterpret_cast<float4*>(out + ((size_t)b0 * SEQ + t) * NS);
            float4* o1 = reinterpret_cast<float4*>(out + ((size_t)b1 * SEQ + t) * NS);
            o0[0] = make_float4(lo[0], lo[1], lo[2],  lo[3]);
            o0[1] = make_float4(lo[4], lo[5], lo[6],  lo[7]);
            o0[2] = make_float4(lo[8], lo[9], lo[10], lo[11]);
            o0[3] = make_float4(lo[12], lo[13], lo[14], lo[15]);
            o1[0] = make_float4(hi[0], hi[1], hi[2],  hi[3]);
            o1[1] = make_float4(hi[4], hi[5], hi[6],  hi[7]);
            o1[2] = make_float4(hi[8], hi[9], hi[10], hi[11]);
            o1[3] = make_float4(hi[12], hi[13], hi[14], hi[15]);
        }
    }
}

// =========================================================================
extern "C" void kernel_launch(void* const* d_in, const int* in_sizes, int n_in,
                              void* d_out, int out_size)
{
    (void)in_sizes; (void)n_in; (void)out_size;
    const float* obs = (const float*)d_in[0];
    const float* inp = (const float*)d_in[1];
    const float* A   = (const float*)d_in[2];
    const float* B   = (const float*)d_in[3];
    const float* C   = (const float*)d_in[4];
    const float* Q   = (const float*)d_in[5];
    const float* R   = (const float*)d_in[6];
    const float* x0  = (const float*)d_in[7];
    float* out = (float*)d_out;

    riccati_kernel<<<1, 256>>>(A, B, C, Q, R);
    fused_kernel<<<NCH, 128>>>(obs, inp, x0, out);
}

// round 12
// speedup vs baseline: 1.2513x; 1.0401x over previous
#include <cuda_runtime.h>
#include <cstdint>
#include <cstddef>

#define SEQ   4096
#define BATCH 256
#define NS    16
#define MS    8
#define US    4
#define LCH   8           // chunk length
#define NCH   512         // chunks
#define GRP   16          // chunks per group
#define NGRP  32          // groups
#define GQ    448         // gain scalars per t: M(256)|N(64)|K(128)

typedef unsigned long long u64;

// ---------------- device scratch ----------------
__device__ __align__(16) float2 d_G2[(size_t)SEQ * GQ];   // duplicated (g,g) pairs
__device__ int d_tlast;                                   // last distinct gain index
__device__ __align__(16) float d_Phi[NCH * 256];
__device__ __align__(16) float d_Psi[NGRP * 256];
__device__ __align__(16) float d_V  [(size_t)NCH  * BATCH * NS];
__device__ __align__(16) float d_GV [(size_t)NGRP * BATCH * NS];
__device__ __align__(16) float d_GS [(size_t)NGRP * BATCH * NS];
__device__ __align__(16) float d_Sst[(size_t)NCH  * BATCH * NS];
// packed per-step zero-start states v_t : [(chunk*LCH+step)*16+q][tid(128)] u64
__device__ __align__(16) u64 d_Vt[(size_t)NCH * LCH * NS * 128];

// ---------------- grid barrier (epoch-based, replay-safe) ----------------
__device__ unsigned int g_cnt = 0;
__device__ volatile unsigned int g_epoch = 0;

__device__ __forceinline__ void gsync(unsigned int target)
{
    __syncthreads();
    if (threadIdx.x == 0) {
        __threadfence();
        unsigned int prev = atomicAdd(&g_cnt, 1u);
        if (prev == gridDim.x - 1u) {
            atomicExch(&g_cnt, 0u);
            __threadfence();
            g_epoch = target;
        } else {
            while (g_epoch != target) __nanosleep(64);
        }
        __threadfence();
    }
    __syncthreads();
}

// ---------------- f32x2 helpers ----------------
__device__ __forceinline__ u64 ffma2(u64 a, u64 b, u64 c) {
    u64 d;
    asm("fma.rn.f32x2 %0, %1, %2, %3;" : "=l"(d) : "l"(a), "l"(b), "l"(c));
    return d;
}
__device__ __forceinline__ u64 fmul2(u64 a, u64 b) {
    u64 d;
    asm("mul.rn.f32x2 %0, %1, %2;" : "=l"(d) : "l"(a), "l"(b));
    return d;
}
__device__ __forceinline__ u64 pack2(float x, float y) {
    u64 r;
    asm("mov.b64 %0, {%1, %2};" : "=l"(r) : "f"(x), "f"(y));
    return r;
}
__device__ __forceinline__ void unpk2(u64 v, float& lo, float& hi) {
    asm("mov.b64 {%0, %1}, %2;" : "=f"(lo), "=f"(hi) : "l"(v));
}

// =========================================================================
// Kernel 1: serial Riccati recursion (one block)
// =========================================================================
__global__ void __launch_bounds__(256) riccati_kernel(
    const float* __restrict__ A, const float* __restrict__ B,
    const float* __restrict__ C, const float* __restrict__ Q,
    const float* __restrict__ R)
{
    __shared__ float sA[256], sB[64], sC[128], sQ[256], sR[64];
    __shared__ float sCA[128], sCB[32], sCQ[128], sSR0[64];
    __shared__ float sP[256], sT1[256], sPp[256], sCT[128], sW[128], sK[128], sSm[64], sSi[64];

    const int tid = threadIdx.x;
    const int i  = tid >> 4;
    const int jc = tid & 15;

    sA[tid] = A[tid];
    sQ[tid] = Q[tid];
    if (tid < 64)  { sB[tid] = B[tid]; sR[tid] = R[tid]; }
    if (tid < 128) sC[tid] = C[tid];
    sP[tid] = (i == jc) ? 1.0f : 0.0f;   // P0 = I
    __syncthreads();

    if (tid < 128) {                      // CA = C*A, CQ = C*Q  (8x16)
        float a = 0.f, q = 0.f;
        int m = tid >> 4, jj = tid & 15;
        #pragma unroll
        for (int k = 0; k < 16; ++k) {
            a += sC[m * 16 + k] * sA[k * 16 + jj];
            q += sC[m * 16 + k] * sQ[k * 16 + jj];
        }
        sCA[tid] = a; sCQ[tid] = q;
    }
    if (tid < 32) {                       // CB = C*B  (8x4)
        float a = 0.f;
        #pragma unroll
        for (int k = 0; k < 16; ++k) a += sC[(tid >> 2) * 16 + k] * sB[k * 4 + (tid & 3)];
        sCB[tid] = a;
    }
    __syncthreads();
    if (tid < 64) {                       // SR0 = CQ*C^T + R (8x8)
        int m = tid >> 3, n = tid & 7;
        float s = sR[tid];
        #pragma unroll
        for (int k = 0; k < 16; ++k) s += sCQ[m * 16 + k] * sC[n * 16 + k];
        sSR0[tid] = s;
    }
    __syncthreads();

    int tconv = SEQ;
    for (int t = 1; t < SEQ; ++t) {
        // (1) T1 = A * P
        float a = 0.f;
        #pragma unroll
        for (int k = 0; k < 16; ++k) a += sA[i * 16 + k] * sP[k * 16 + jc];
        sT1[tid] = a;
        __syncthreads();
        // (2) Ppri = T1*A^T + Q (all)  ;  CT = C*T1 (tid<128)
        a = sQ[tid];
        #pragma unroll
        for (int k = 0; k < 16; ++k) a += sT1[i * 16 + k] * sA[jc * 16 + k];
        sPp[tid] = a;
        if (tid < 128) {
            int m = tid >> 4, jj = tid & 15;
            float w = 0.f;
            #pragma unroll
            for (int k = 0; k < 16; ++k) w += sC[m * 16 + k] * sT1[k * 16 + jj];
            sCT[tid] = w;
        }
        __syncthreads();
        // (3) W = CT*A^T + CQ (tid<128)  ;  S = CT*CA^T + SR0 (tid 128..191)
        if (tid < 128) {
            int m = tid >> 4, jj = tid & 15;
            float w = sCQ[tid];
            #pragma unroll
            for (int k = 0; k < 16; ++k) w += sCT[m * 16 + k] * sA[jj * 16 + k];
            sW[tid] = w;
        } else if (tid < 192) {
            int q = tid - 128, m = q >> 3, n = q & 7;
            float s = sSR0[q];
            #pragma unroll
            for (int k = 0; k < 16; ++k) s += sCT[m * 16 + k] * sCA[n * 16 + k];
            sSm[q] = s;
        }
        __syncthreads();
        // (4) Sinv: warp-synchronous Gauss-Jordan (8 lanes, SPD)
        if (tid < 8) {
            float row[16];
            #pragma unroll
            for (int c = 0; c < 8; ++c) { row[c] = sSm[tid * 8 + c]; row[c + 8] = (c == tid) ? 1.f : 0.f; }
            #pragma unroll
            for (int p = 0; p < 8; ++p) {
                float pv  = __shfl_sync(0xFFu, row[p], p, 8);
                float f   = row[p];
                float inv = 1.0f / pv;
                #pragma unroll
                for (int c = 0; c < 16; ++c) {
                    float pr = __shfl_sync(0xFFu, row[c], p, 8) * inv;
                    row[c] = (tid == p) ? pr : (row[c] - f * pr);
                }
            }
            #pragma unroll
            for (int c = 0; c < 8; ++c) sSi[tid * 8 + c] = row[c + 8];
        }
        __syncthreads();
        // (5) K = W^T * Sinv  (16x8)
        if (tid < 128) {
            int ii = tid >> 3, m = tid & 7;
            float kk = 0.f;
            #pragma unroll
            for (int n = 0; n < 8; ++n) kk += sW[n * 16 + ii] * sSi[n * 8 + m];
            sK[tid] = kk;
        }
        __syncthreads();
        // (6) outputs + Ppost + convergence
        {
            float mm = sA[tid];                         // M = A - K*CA
            #pragma unroll
            for (int m = 0; m < 8; ++m) mm -= sK[i * 8 + m] * sCA[m * 16 + jc];
            d_G2[(size_t)t * GQ + tid] = make_float2(mm, mm);
        }
        if (tid < 64) {                                 // N = B - K*CB
            int ii = tid >> 2, u = tid & 3;
            float nn = sB[tid];
            #pragma unroll
            for (int m = 0; m < 8; ++m) nn -= sK[ii * 8 + m] * sCB[m * 4 + u];
            d_G2[(size_t)t * GQ + 256 + tid] = make_float2(nn, nn);
        }
        if (tid < 128) {
            float kk = sK[tid];
            d_G2[(size_t)t * GQ + 320 + tid] = make_float2(kk, kk);
        }
        float pn = sPp[tid];                            // Ppost = Ppri - K*W
        #pragma unroll
        for (int m = 0; m < 8; ++m) pn -= sK[i * 8 + m] * sW[m * 16 + jc];
        int pred = fabsf(pn - sP[tid]) < 1e-5f;
        sP[tid] = pn;
        int conv = __syncthreads_and(pred);
        if (conv) { tconv = t + 1; break; }
    }
    __syncthreads();
    if (tid == 0) d_tlast = (tconv < SEQ) ? (tconv - 1) : (SEQ - 1);
}

// =========================================================================
// drive term:  c_i = N_i·u + K_i·z
// =========================================================================
__device__ __forceinline__ void compute_c(u64 c[NS], const u64* __restrict__ g,
                                          const u64 zz[MS], const u64 uu[US])
{
    #pragma unroll
    for (int i = 0; i < NS; ++i) {
        const ulonglong2* gn = reinterpret_cast<const ulonglong2*>(g + 256 + i * 4);
        const ulonglong2* gk = reinterpret_cast<const ulonglong2*>(g + 320 + i * 8);
        ulonglong2 n0 = gn[0], n1 = gn[1];
        u64 a = fmul2(n0.x, uu[0]);
        a = ffma2(n0.y, uu[1], a);
        a = ffma2(n1.x, uu[2], a);
        a = ffma2(n1.y, uu[3], a);
        ulonglong2 k0 = gk[0], k1 = gk[1], k2 = gk[2], k3 = gk[3];
        a = ffma2(k0.x, zz[0], a); a = ffma2(k0.y, zz[1], a);
        a = ffma2(k1.x, zz[2], a); a = ffma2(k1.y, zz[3], a);
        a = ffma2(k2.x, zz[4], a); a = ffma2(k2.y, zz[5], a);
        a = ffma2(k3.x, zz[6], a); a = ffma2(k3.y, zz[7], a);
        c[i] = a;
    }
}

// recursion step:  x <- M x + c   (128-bit shared loads)
__device__ __forceinline__ void kstepm(u64 x[NS], const u64* __restrict__ g,
                                       const u64 c[NS])
{
    u64 acc[NS];
    #pragma unroll
    for (int i = 0; i < NS; ++i) {
        const ulonglong2* gm = reinterpret_cast<const ulonglong2*>(g + i * 16);
        u64 a = c[i];
        #pragma unroll
        for (int k = 0; k < 8; ++k) {
            ulonglong2 m2 = gm[k];
            a = ffma2(m2.x, x[2 * k],     a);
            a = ffma2(m2.y, x[2 * k + 1], a);
        }
        acc[i] = a;
    }
    #pragma unroll
    for (int i = 0; i < NS; ++i) x[i] = acc[i];
}

__device__ __forceinline__ void load_zu2(const float* __restrict__ obs,
                                         const float* __restrict__ inp,
                                         int b0, int b1, int t,
                                         u64 zz[MS], u64 uu[US])
{
    const float4* z0p = reinterpret_cast<const float4*>(obs + ((size_t)b0 * SEQ + t) * MS);
    const float4* z1p = reinterpret_cast<const float4*>(obs + ((size_t)b1 * SEQ + t) * MS);
    float4 a0 = __ldg(z0p), a1 = __ldg(z0p + 1);
    float4 c0 = __ldg(z1p), c1 = __ldg(z1p + 1);
    zz[0] = pack2(a0.x, c0.x); zz[1] = pack2(a0.y, c0.y);
    zz[2] = pack2(a0.z, c0.z); zz[3] = pack2(a0.w, c0.w);
    zz[4] = pack2(a1.x, c1.x); zz[5] = pack2(a1.y, c1.y);
    zz[6] = pack2(a1.z, c1.z); zz[7] = pack2(a1.w, c1.w);
    float4 u0 = __ldg(reinterpret_cast<const float4*>(inp + ((size_t)b0 * SEQ + t) * US));
    float4 u1 = __ldg(reinterpret_cast<const float4*>(inp + ((size_t)b1 * SEQ + t) * US));
    uu[0] = pack2(u0.x, u1.x); uu[1] = pack2(u0.y, u1.y);
    uu[2] = pack2(u0.z, u1.z); uu[3] = pack2(u0.w, u1.w);
}

// ---------------- 16-lane shuffle matvec with register-passed rows ----------
__device__ __forceinline__ float affine16r(float4 p0, float4 p1, float4 p2, float4 p3,
                                           float v, float s)
{
    float a = v;
    a += p0.x * __shfl_sync(0xFFFFFFFFu, s, 0, 16)  + p0.y * __shfl_sync(0xFFFFFFFFu, s, 1, 16)
       + p0.z * __shfl_sync(0xFFFFFFFFu, s, 2, 16)  + p0.w * __shfl_sync(0xFFFFFFFFu, s, 3, 16);
    a += p1.x * __shfl_sync(0xFFFFFFFFu, s, 4, 16)  + p1.y * __shfl_sync(0xFFFFFFFFu, s, 5, 16)
       + p1.z * __shfl_sync(0xFFFFFFFFu, s, 6, 16)  + p1.w * __shfl_sync(0xFFFFFFFFu, s, 7, 16);
    a += p2.x * __shfl_sync(0xFFFFFFFFu, s, 8, 16)  + p2.y * __shfl_sync(0xFFFFFFFFu, s, 9, 16)
       + p2.z * __shfl_sync(0xFFFFFFFFu, s, 10, 16) + p2.w * __shfl_sync(0xFFFFFFFFu, s, 11, 16);
    a += p3.x * __shfl_sync(0xFFFFFFFFu, s, 12, 16) + p3.y * __shfl_sync(0xFFFFFFFFu, s, 13, 16)
       + p3.z * __shfl_sync(0xFFFFFFFFu, s, 14, 16) + p3.w * __shfl_sync(0xFFFFFFFFu, s, 15, 16);
    return a;
}

// =========================================================================
// Kernel 2: fused persistent kernel.
//  P1: stage gains + prefix matrices (smem) + vpass (stores v_t packed)
//  P2: psi (32 dedicated blocks) | gscanA (480 blocks, prefetched)
//  P3: gscanB (32 blocks, prefetched serial scan)
//  P4a: gscanC (all blocks, prefetched)
//  P4b: outpass — out[t] = v_t + Pfx_s · s_j   (NO serial chain)
// =========================================================================
__global__ void __launch_bounds__(128, 4) fused_kernel(
    const float* __restrict__ obs, const float* __restrict__ inp,
    const float* __restrict__ x0, float* __restrict__ out)
{
    __shared__ __align__(16) u64 sG[LCH][GQ];      // 28672 B gains (dup pairs)
    __shared__ __align__(16) u64 sPfx[LCH][256];   // 16384 B prefix matrices (dup pairs)
    __shared__ float sPh[2][256];                  // 2048 B psi ping-pong

    const int j   = blockIdx.x;
    const int tid = threadIdx.x;
    const int b0  = tid, b1 = tid + 128;
    const int t0  = j * LCH + 1;
    const int steps = (t0 + LCH <= SEQ) ? LCH : (SEQ - t0);

    const unsigned int E0 = g_epoch;     // per-thread; epoch can't advance
    const int tlast = d_tlast;           // until all blocks reach first gsync

    // ---------------- P1a: stage all LCH gain sets (clamped index) ----------
    #pragma unroll
    for (int s = 0; s < LCH; ++s) {
        int tt = t0 + s; if (tt > tlast) tt = tlast;
        const float4* src = reinterpret_cast<const float4*>(&d_G2[(size_t)tt * GQ]);
        reinterpret_cast<float4*>(sG[s])[tid] = __ldg(src + tid);      // prior launch — __ldg legal
        if (tid < 96) reinterpret_cast<float4*>(sG[s])[128 + tid] = __ldg(src + 128 + tid);
    }
    __syncthreads();

    // ---------------- P1b: prefix matrices Pfx_s = M_s ··· M_0 --------------
    {
        sPfx[0][tid]       = sG[0][tid];        // M part occupies first 256 u64 (dup)
        sPfx[0][tid + 128] = sG[0][tid + 128];
        __syncthreads();
        for (int s = 1; s < steps; ++s) {
            const float* Ms = reinterpret_cast<const float*>(sG[s]);
            const float* Pp = reinterpret_cast<const float*>(sPfx[s - 1]);
            #pragma unroll
            for (int h = 0; h < 2; ++h) {
                int e = tid + h * 128, ii = e >> 4, jc = e & 15;
                float a = 0.f;
                #pragma unroll
                for (int k = 0; k < 16; ++k) a += Ms[2 * (ii * 16 + k)] * Pp[2 * (k * 16 + jc)];
                sPfx[s][e] = pack2(a, a);
            }
            __syncthreads();
        }
        const float* Pl = reinterpret_cast<const float*>(sPfx[steps - 1]);
        d_Phi[j * 256 + tid]       = Pl[2 * tid];
        d_Phi[j * 256 + tid + 128] = Pl[2 * (tid + 128)];
    }

    // ---------------- P1c: vpass; store per-step v_t packed -----------------
    {
        u64 x[NS];
        #pragma unroll
        for (int q = 0; q < NS; ++q) x[q] = 0ull;
        for (int s = 0; s < steps; ++s) {
            u64 zz[MS], uu[US], c[NS];
            load_zu2(obs, inp, b0, b1, t0 + s, zz, uu);
            compute_c(c, sG[s], zz, uu);
            kstepm(x, sG[s], c);
            u64* vb = &d_Vt[((size_t)(j * LCH + s) * NS) * 128 + tid];
            #pragma unroll
            for (int q = 0; q < NS; ++q) vb[q * 128] = x[q];
        }
        float lo[NS], hi[NS];
        #pragma unroll
        for (int q = 0; q < NS; ++q) unpk2(x[q], lo[q], hi[q]);
        float4* v0 = reinterpret_cast<float4*>(&d_V[((size_t)j * BATCH + b0) * NS]);
        float4* v1 = reinterpret_cast<float4*>(&d_V[((size_t)j * BATCH + b1) * NS]);
        v0[0] = make_float4(lo[0], lo[1], lo[2],  lo[3]);
        v0[1] = make_float4(lo[4], lo[5], lo[6],  lo[7]);
        v0[2] = make_float4(lo[8], lo[9], lo[10], lo[11]);
        v0[3] = make_float4(lo[12], lo[13], lo[14], lo[15]);
        v1[0] = make_float4(hi[0], hi[1], hi[2],  hi[3]);
        v1[1] = make_float4(hi[4], hi[5], hi[6],  hi[7]);
        v1[2] = make_float4(hi[8], hi[9], hi[10], hi[11]);
        v1[3] = make_float4(hi[12], hi[13], hi[14], hi[15]);
    }
    if (j == 0) {       // out[b][0] = x0 for every batch
        const float4* xp = reinterpret_cast<const float4*>(x0);
        float4 x00 = __ldg(xp), x01 = __ldg(xp + 1), x02 = __ldg(xp + 2), x03 = __ldg(xp + 3);
        float4* o0 = reinterpret_cast<float4*>(out + (size_t)b0 * SEQ * NS);
        float4* o1 = reinterpret_cast<float4*>(out + (size_t)b1 * SEQ * NS);
        o0[0] = x00; o0[1] = x01; o0[2] = x02; o0[3] = x03;
        o1[0] = x00; o1[1] = x01; o1[2] = x02; o1[3] = x03;
    }

    gsync(E0 + 1);

    // ---------------- P2: psi (blocks 480..511 only) | gscanA (0..479) ------
    if (j >= NCH - NGRP) {
        const int g = j - (NCH - NGRP);
        sPh[0][tid]       = d_Phi[(g * GRP) * 256 + tid];
        sPh[0][tid + 128] = d_Phi[(g * GRP) * 256 + tid + 128];
        __syncthreads();
        int pp = 0;
        for (int c = 1; c < GRP; ++c) {
            const float* Ms = &d_Phi[(g * GRP + c) * 256];
            #pragma unroll
            for (int h = 0; h < 2; ++h) {
                int e = tid + h * 128, ii = e >> 4, jc = e & 15;
                float a = 0.f;
                #pragma unroll
                for (int k = 0; k < 16; ++k) a += Ms[ii * 16 + k] * sPh[pp][k * 16 + jc];
                sPh[pp ^ 1][e] = a;
            }
            __syncthreads();
            pp ^= 1;
        }
        d_Psi[g * 256 + tid]       = sPh[pp][tid];
        d_Psi[g * 256 + tid + 128] = sPh[pp][tid + 128];
    } else {
        const int i = tid & 15;
        const int ntask = (j < 64) ? 3 : 2;
        for (int r = 0; r < ntask; ++r) {
            const int T = (r == 0) ? j : ((r == 1) ? j + (NCH - NGRP) : 2 * (NCH - NGRP) + j);
            const int g = T >> 5, sub = T & 31;
            const int b = sub * 8 + (tid >> 4);
            float s = 0.f;
            int ch = g * GRP;
            float v = d_V[((size_t)ch * BATCH + b) * NS + i];
            const float4* pr = reinterpret_cast<const float4*>(&d_Phi[ch * 256 + i * 16]);
            float4 p0 = pr[0], p1 = pr[1], p2 = pr[2], p3 = pr[3];
            #pragma unroll
            for (int c = 0; c < GRP; ++c) {
                float vn = 0.f; float4 q0, q1, q2, q3;
                if (c < GRP - 1) {                              // prefetch next chunk
                    const int chn = ch + 1;
                    vn = d_V[((size_t)chn * BATCH + b) * NS + i];
                    const float4* qn = reinterpret_cast<const float4*>(&d_Phi[chn * 256 + i * 16]);
                    q0 = qn[0]; q1 = qn[1]; q2 = qn[2]; q3 = qn[3];
                }
                s = affine16r(p0, p1, p2, p3, v, s);
                v = vn; p0 = q0; p1 = q1; p2 = q2; p3 = q3; ++ch;
            }
            d_GV[((size_t)g * BATCH + b) * NS + i] = s;
        }
    }

    gsync(E0 + 2);

    // ---------------- P3: gscanB (blocks 0..31, serial over 32 groups) ------
    if (j < 32) {
        const int b = j * 8 + (tid >> 4);
        const int i = tid & 15;
        float s = __ldg(x0 + i);
        float v = d_GV[((size_t)0 * BATCH + b) * NS + i];
        const float4* pr = reinterpret_cast<const float4*>(&d_Psi[0 * 256 + i * 16]);
        float4 p0 = pr[0], p1 = pr[1], p2 = pr[2], p3 = pr[3];
        #pragma unroll
        for (int g = 0; g < NGRP; ++g) {
            float vn = 0.f; float4 q0, q1, q2, q3;
            if (g < NGRP - 1) {                                 // prefetch next group
                vn = d_GV[((size_t)(g + 1) * BATCH + b) * NS + i];
                const float4* qn = reinterpret_cast<const float4*>(&d_Psi[(g + 1) * 256 + i * 16]);
                q0 = qn[0]; q1 = qn[1]; q2 = qn[2]; q3 = qn[3];
            }
            d_GS[((size_t)g * BATCH + b) * NS + i] = s;
            s = affine16r(p0, p1, p2, p3, v, s);
            v = vn; p0 = q0; p1 = q1; p2 = q2; p3 = q3;
        }
    }

    gsync(E0 + 3);

    // ---------------- P4a: gscanC (all blocks, 2 tasks, prefetched) ---------
    {
        const int i = tid & 15;
        #pragma unroll
        for (int rep = 0; rep < 2; ++rep) {
            const int T = j + rep * NCH;
            const int g = T >> 5, sub = T & 31;
            const int b = sub * 8 + (tid >> 4);
            float s = d_GS[((size_t)g * BATCH + b) * NS + i];
            int ch = g * GRP;
            float v = d_V[((size_t)ch * BATCH + b) * NS + i];
            const float4* pr = reinterpret_cast<const float4*>(&d_Phi[ch * 256 + i * 16]);
            float4 p0 = pr[0], p1 = pr[1], p2 = pr[2], p3 = pr[3];
            #pragma unroll
            for (int c = 0; c < GRP; ++c) {
                float vn = 0.f; float4 q0, q1, q2, q3;
                if (c < GRP - 1) {
                    const int chn = ch + 1;
                    vn = d_V[((size_t)chn * BATCH + b) * NS + i];
                    const float4* qn = reinterpret_cast<const float4*>(&d_Phi[chn * 256 + i * 16]);
                    q0 = qn[0]; q1 = qn[1]; q2 = qn[2]; q3 = qn[3];
                }
                d_Sst[((size_t)ch * BATCH + b) * NS + i] = s;
                s = affine16r(p0, p1, p2, p3, v, s);
                v = vn; p0 = q0; p1 = q1; p2 = q2; p3 = q3; ++ch;
            }
        }
    }

    gsync(E0 + 4);

    // ---------------- P4b: outpass — out[t] = v_t + Pfx_s · s_j -------------
    {
        u64 sj[NS];
        {
            const float4* s0 = reinterpret_cast<const float4*>(&d_Sst[((size_t)j * BATCH + b0) * NS]);
            const float4* s1 = reinterpret_cast<const float4*>(&d_Sst[((size_t)j * BATCH + b1) * NS]);
            float4 q0 = s0[0], q1 = s0[1], q2 = s0[2], q3 = s0[3];
            float4 r0 = s1[0], r1 = s1[1], r2 = s1[2], r3 = s1[3];
            sj[0]  = pack2(q0.x, r0.x); sj[1]  = pack2(q0.y, r0.y); sj[2]  = pack2(q0.z, r0.z); sj[3]  = pack2(q0.w, r0.w);
            sj[4]  = pack2(q1.x, r1.x); sj[5]  = pack2(q1.y, r1.y); sj[6]  = pack2(q1.z, r1.z); sj[7]  = pack2(q1.w, r1.w);
            sj[8]  = pack2(q2.x, r2.x); sj[9]  = pack2(q2.y, r2.y); sj[10] = pack2(q2.z, r2.z); sj[11] = pack2(q2.w, r2.w);
            sj[12] = pack2(q3.x, r3.x); sj[13] = pack2(q3.y, r3.y); sj[14] = pack2(q3.z, r3.z); sj[15] = pack2(q3.w, r3.w);
        }
        for (int s = 0; s < steps; ++s) {
            const int t = t0 + s;
            u64 v[NS];
            {
                const u64* vb = &d_Vt[((size_t)(j * LCH + s) * NS) * 128 + tid];
                #pragma unroll
                for (int q = 0; q < NS; ++q) v[q] = vb[q * 128];
            }
            const ulonglong2* P = reinterpret_cast<const ulonglong2*>(sPfx[s]);
            #pragma unroll
            for (int i = 0; i < NS; ++i) {
                u64 a = v[i];
                #pragma unroll
                for (int k = 0; k < 8; ++k) {
                    ulonglong2 p2v = P[i * 8 + k];
                    a = ffma2(p2v.x, sj[2 * k],     a);
                    a = ffma2(p2v.y, sj[2 * k + 1], a);
                }
                v[i] = a;
            }
            float lo[NS], hi[NS];
            #pragma unroll
            for (int q = 0; q < NS; ++q) unpk2(v[q], lo[q], hi[q]);
            float4* o0 = reinterpret_cast<float4*>(out + ((size_t)b0 * SEQ + t) * NS);
            float4* o1 = reinterpret_cast<float4*>(out + ((size_t)b1 * SEQ + t) * NS);
            o0[0] = make_float4(lo[0], lo[1], lo[2],  lo[3]);
            o0[1] = make_float4(lo[4], lo[5], lo[6],  lo[7]);
            o0[2] = make_float4(lo[8], lo[9], lo[10], lo[11]);
            o0[3] = make_float4(lo[12], lo[13], lo[14], lo[15]);
            o1[0] = make_float4(hi[0], hi[1], hi[2],  hi[3]);
            o1[1] = make_float4(hi[4], hi[5], hi[6],  hi[7]);
            o1[2] = make_float4(hi[8], hi[9], hi[10], hi[11]);
            o1[3] = make_float4(hi[12], hi[13], hi[14], hi[15]);
        }
    }
}

// =========================================================================
extern "C" void kernel_launch(void* const* d_in, const int* in_sizes, int n_in,
                              void* d_out, int out_size)
{
    (void)in_sizes; (void)n_in; (void)out_size;
    const float* obs = (const float*)d_in[0];
    const float* inp = (const float*)d_in[1];
    const float* A   = (const float*)d_in[2];
    const float* B   = (const float*)d_in[3];
    const float* C   = (const float*)d_in[4];
    const float* Q   = (const float*)d_in[5];
    const float* R   = (const float*)d_in[6];
    const float* x0  = (const float*)d_in[7];
    float* out = (float*)d_out;

    riccati_kernel<<<1, 256>>>(A, B, C, Q, R);
    fused_kernel<<<NCH, 128>>>(obs, inp, x0, out);
}